// round 13
// baseline (speedup 1.0000x reference)
#include <cuda_runtime.h>
#include <cuda_bf16.h>
#include <math.h>

#define NB   8
#define CCH  256
#define HH   128
#define WW   128
#define HWSZ 16384
#define QKD  64

typedef unsigned int u32;
typedef __nv_bfloat16 bf16;

// ---------------- scratch ----------------
__device__ uint4 g_Wf[24 * 16 * 32];                    // W mma-fragment layout
__device__ __align__(16) bf16 g_attn[(size_t)NB * CCH * HWSZ];  // pre-gate out, bf16
__device__ float g_psum[(size_t)NB * CCH * HH];
__device__ float g_pmax[(size_t)NB * CCH * HH];
__device__ float g_gate[NB * CCH];

// ---------------- helpers ----------------
__device__ __forceinline__ u32 smem_u32(const void* p) {
    u32 a;
    asm("{.reg .u64 t; cvta.to.shared.u64 t, %1; cvt.u32.u64 %0, t;}"
        : "=r"(a) : "l"(p));
    return a;
}
__device__ __forceinline__ void ldsm4(u32* r, u32 a) {
    asm volatile("ldmatrix.sync.aligned.m8n8.x4.shared.b16 {%0,%1,%2,%3},[%4];"
        : "=r"(r[0]), "=r"(r[1]), "=r"(r[2]), "=r"(r[3]) : "r"(a));
}
__device__ __forceinline__ void ldsm4t(u32* r, u32 a) {
    asm volatile("ldmatrix.sync.aligned.m8n8.x4.trans.shared.b16 {%0,%1,%2,%3},[%4];"
        : "=r"(r[0]), "=r"(r[1]), "=r"(r[2]), "=r"(r[3]) : "r"(a));
}
__device__ __forceinline__ void mma_bf(float* d, const u32* a, const u32* b) {
    asm volatile(
        "mma.sync.aligned.m16n8k16.row.col.f32.bf16.bf16.f32 "
        "{%0,%1,%2,%3},{%4,%5,%6,%7},{%8,%9},{%0,%1,%2,%3};"
        : "+f"(d[0]), "+f"(d[1]), "+f"(d[2]), "+f"(d[3])
        : "r"(a[0]), "r"(a[1]), "r"(a[2]), "r"(a[3]), "r"(b[0]), "r"(b[1]));
}
__device__ __forceinline__ u32 packbf(float lo, float hi) {
    u32 r; asm("cvt.rn.bf16x2.f32 %0,%1,%2;" : "=r"(r) : "f"(hi), "f"(lo));
    return r;
}
__device__ __forceinline__ void cp16(u32 dst, const void* src) {
    asm volatile("cp.async.cg.shared.global [%0], [%1], 16;" :: "r"(dst), "l"(src));
}
#define CP_COMMIT() asm volatile("cp.async.commit_group;" ::: "memory")
#define CP_WAIT1()  asm volatile("cp.async.wait_group 1;" ::: "memory")

// ---------------------------------------------------------------------------
__global__ void convert_w(const float* __restrict__ Wq,
                          const float* __restrict__ Wk,
                          const float* __restrict__ Wv)
{
    int tid = blockIdx.x * 256 + threadIdx.x;   // 0..12287
    int mt  = tid >> 9;
    int rem = tid & 511;
    int kt  = rem >> 5;
    int l   = rem & 31;
    int g2 = l >> 2, tq2 = l & 3;
    int r0 = mt * 16 + g2;
    int c0 = kt * 16 + tq2 * 2;

    const float* S; int roff;
    if (r0 < 64)       { S = Wq; roff = r0; }
    else if (r0 < 128) { S = Wk; roff = r0 - 64; }
    else               { S = Wv; roff = r0 - 128; }
    const float* p0 = S + (size_t)roff * CCH;
    const float* p8 = p0 + 8 * CCH;

    uint4 o;
    o.x = packbf(p0[c0],     p0[c0 + 1]);
    o.y = packbf(p8[c0],     p8[c0 + 1]);
    o.z = packbf(p0[c0 + 8], p0[c0 + 9]);
    o.w = packbf(p8[c0 + 8], p8[c0 + 9]);
    g_Wf[tid] = o;
}

// ---------------------------------------------------------------------------
#define XT_PITCH 136
#define QP       136
#define SMEM_TOTAL 211456   // 178688 + 2*16384 staging

__global__ __launch_bounds__(256, 1) void fused_attn(const float* __restrict__ x)
{
    extern __shared__ char smc[];
    bf16*  xt    = (bf16*)smc;                  // [256][136] bf16
    bf16*  qk_s  = (bf16*)(smc + 69632);        // [128][136] bf16
    bf16*  att_s = qk_s;                        // overlay after logits
    bf16*  v_s   = (bf16*)(smc + 104448);       // [256][136] bf16
    float* psum  = (float*)(smc + 174080);      // [128][4]
    float* pmax  = psum + 512;                  // [128][4]
    float* inv_s = (float*)(smc + 178176);      // [128]
    float* xf32  = (float*)(smc + 178688);      // 2 x [32][128] fp32 staging

    bf16* outb = g_attn;

    int nh = blockIdx.x, n = nh >> 7, h = nh & 127;
    int t = threadIdx.x, l = t & 31, w = t >> 5;
    int m0 = (w & 1) * 64, n0 = (w >> 1) * 32;

    const float* xg = x + ((size_t)n * CCH * HH + h) * WW;
    u32 xf_base = smem_u32(xf32);

    // ---- prologue: issue chunks 0,1 ----
#pragma unroll
    for (int ch = 0; ch < 2; ch++) {
#pragma unroll
        for (int q = 0; q < 4; q++) {
            int e = t + q * 256;
            int c = e >> 5, i4 = (e & 31) << 2;
            cp16(xf_base + (ch & 1) * 16384 + (c * 128 + i4) * 4,
                 xg + ((size_t)(ch * 32 + c) * HWSZ) + i4);
        }
        CP_COMMIT();
    }

    // ---- pipelined x-convert + ALL THREE projection GEMMs fused ----
    // acc3[blk]: blk 0 = qk, 1 = v rows 0-127, 2 = v rows 128-255
    float acc3[3][4][4][4];
#pragma unroll
    for (int bk = 0; bk < 3; bk++)
#pragma unroll
        for (int a = 0; a < 4; a++)
#pragma unroll
            for (int b = 0; b < 4; b++)
#pragma unroll
                for (int c = 0; c < 4; c++) acc3[bk][a][b][c] = 0.f;

    int mt0 = (m0 >> 4);

#pragma unroll 1
    for (int ch = 0; ch < 8; ch++) {
        CP_WAIT1();
        __syncthreads();                         // chunk ch visible to all

        // convert staged fp32 -> bf16 xt rows [ch*32, ch*32+32)
        const float* src = xf32 + (ch & 1) * 4096;
#pragma unroll
        for (int q = 0; q < 4; q++) {
            int e = t + q * 256;
            int c = e >> 5, i4 = (e & 31) << 2;
            float4 v4 = *(const float4*)(src + c * 128 + i4);
            uint2 o;
            o.x = packbf(v4.x, v4.y);
            o.y = packbf(v4.z, v4.w);
            *(uint2*)(xt + (ch * 32 + c) * XT_PITCH + i4) = o;
        }
        __syncthreads();                         // buffer free + xt chunk ready

        if (ch < 6) {
#pragma unroll
            for (int q = 0; q < 4; q++) {
                int e = t + q * 256;
                int c = e >> 5, i4 = (e & 31) << 2;
                cp16(xf_base + (ch & 1) * 16384 + (c * 128 + i4) * 4,
                     xg + ((size_t)((ch + 2) * 32 + c) * HWSZ) + i4);
            }
            CP_COMMIT();
        }

        // fused GEMMs: 2 kt steps on this chunk, B frags shared by 3 A blocks
#pragma unroll
        for (int kt2 = 0; kt2 < 2; kt2++) {
            int kt = ch * 2 + kt2;
            int kk = kt * 16;
            u32 b[4][2];
            int br  = kk + ((l >> 3) & 1) * 8 + (l & 7);
            int bcl = (l >> 4) * 8;
#pragma unroll
            for (int bi = 0; bi < 2; bi++) {
                u32 r4[4];
                ldsm4t(r4, smem_u32(xt + br * XT_PITCH + n0 + bi * 16 + bcl));
                b[bi * 2][0] = r4[0]; b[bi * 2][1] = r4[1];
                b[bi * 2 + 1][0] = r4[2]; b[bi * 2 + 1][1] = r4[3];
            }
#pragma unroll
            for (int bk = 0; bk < 3; bk++) {
                int mtb = bk * 8 + mt0;
#pragma unroll
                for (int mf = 0; mf < 4; mf++) {
                    u32 a[4];
                    uint4 av = g_Wf[(size_t)((mtb + mf) * 16 + kt) * 32 + l];
                    a[0] = av.x; a[1] = av.y; a[2] = av.z; a[3] = av.w;
#pragma unroll
                    for (int nf = 0; nf < 4; nf++)
                        mma_bf(acc3[bk][mf][nf], a, b[nf]);
                }
            }
        }
    }

    // ---- epilogues: acc3 -> qk_s / v_s ----
    {
        int g = l >> 2, tq = l & 3;
#pragma unroll
        for (int bk = 0; bk < 3; bk++) {
            bf16* dst = (bk == 0) ? qk_s : (v_s + (size_t)(bk - 1) * 128 * QP);
#pragma unroll
            for (int mf = 0; mf < 4; mf++)
#pragma unroll
                for (int nf = 0; nf < 4; nf++) {
                    int col = n0 + nf * 8 + tq * 2;
                    *(u32*)(dst + (m0 + mf * 16 + g) * QP + col)     = packbf(acc3[bk][mf][nf][0], acc3[bk][mf][nf][1]);
                    *(u32*)(dst + (m0 + mf * 16 + g + 8) * QP + col) = packbf(acc3[bk][mf][nf][2], acc3[bk][mf][nf][3]);
                }
        }
    }
    __syncthreads();

    // ---- logits in registers + register softmax ----
    {
        float acc[4][4][4];
#pragma unroll
        for (int a = 0; a < 4; a++)
#pragma unroll
            for (int b = 0; b < 4; b++)
#pragma unroll
                for (int c = 0; c < 4; c++) acc[a][b][c] = 0.f;

        const bf16* k_s = qk_s + 64 * QP;
#pragma unroll
        for (int ks = 0; ks < 4; ks++) {
            int k0 = ks * 16;
            u32 a[4][4], b[4][2];
            int ar  = k0 + ((l >> 4) << 3) + (l & 7);
            int acl = ((l >> 3) & 1) * 8;
#pragma unroll
            for (int mf = 0; mf < 4; mf++)
                ldsm4t(a[mf], smem_u32(qk_s + ar * QP + m0 + mf * 16 + acl));
            int br  = k0 + ((l >> 3) & 1) * 8 + (l & 7);
            int bcl = (l >> 4) * 8;
#pragma unroll
            for (int bi = 0; bi < 2; bi++) {
                u32 r4[4];
                ldsm4t(r4, smem_u32(k_s + br * QP + n0 + bi * 16 + bcl));
                b[bi * 2][0] = r4[0]; b[bi * 2][1] = r4[1];
                b[bi * 2 + 1][0] = r4[2]; b[bi * 2 + 1][1] = r4[3];
            }
#pragma unroll
            for (int mf = 0; mf < 4; mf++)
#pragma unroll
                for (int nf = 0; nf < 4; nf++)
                    mma_bf(acc[mf][nf], a[mf], b[nf]);
        }

        int g = l >> 2, tq = l & 3, wj = w >> 1;

#pragma unroll
        for (int mf = 0; mf < 4; mf++) {
            float rl = -1e30f, rh = -1e30f;
#pragma unroll
            for (int nf = 0; nf < 4; nf++) {
                rl = fmaxf(rl, fmaxf(acc[mf][nf][0], acc[mf][nf][1]));
                rh = fmaxf(rh, fmaxf(acc[mf][nf][2], acc[mf][nf][3]));
            }
            rl = fmaxf(rl, __shfl_xor_sync(0xffffffffu, rl, 1));
            rl = fmaxf(rl, __shfl_xor_sync(0xffffffffu, rl, 2));
            rh = fmaxf(rh, __shfl_xor_sync(0xffffffffu, rh, 1));
            rh = fmaxf(rh, __shfl_xor_sync(0xffffffffu, rh, 2));
            if (tq == 0) {
                pmax[(m0 + mf * 16 + g) * 4 + wj]     = rl;
                pmax[(m0 + mf * 16 + g + 8) * 4 + wj] = rh;
            }
        }
        __syncthreads();   // max partials visible; ALL qk ldsm reads complete

#pragma unroll
        for (int mf = 0; mf < 4; mf++) {
            int il = m0 + mf * 16 + g, ih = il + 8;
            float Ml = fmaxf(fmaxf(pmax[il * 4], pmax[il * 4 + 1]),
                             fmaxf(pmax[il * 4 + 2], pmax[il * 4 + 3]));
            float Mh = fmaxf(fmaxf(pmax[ih * 4], pmax[ih * 4 + 1]),
                             fmaxf(pmax[ih * 4 + 2], pmax[ih * 4 + 3]));
            float sl = 0.f, sh = 0.f;
#pragma unroll
            for (int nf = 0; nf < 4; nf++) {
                float e0 = __expf(acc[mf][nf][0] - Ml);
                float e1 = __expf(acc[mf][nf][1] - Ml);
                float e2 = __expf(acc[mf][nf][2] - Mh);
                float e3 = __expf(acc[mf][nf][3] - Mh);
                sl += e0 + e1; sh += e2 + e3;
                int j = n0 + nf * 8 + tq * 2;
                *(u32*)(att_s + il * QP + j) = packbf(e0, e1);
                *(u32*)(att_s + ih * QP + j) = packbf(e2, e3);
            }
            sl += __shfl_xor_sync(0xffffffffu, sl, 1);
            sl += __shfl_xor_sync(0xffffffffu, sl, 2);
            sh += __shfl_xor_sync(0xffffffffu, sh, 1);
            sh += __shfl_xor_sync(0xffffffffu, sh, 2);
            if (tq == 0) {
                psum[il * 4 + wj] = sl;
                psum[ih * 4 + wj] = sh;
            }
        }
        __syncthreads();

        if (t < 128)
            inv_s[t] = 1.f / (psum[t * 4] + psum[t * 4 + 1] + psum[t * 4 + 2] + psum[t * 4 + 3]);
        __syncthreads();
    }

    // ---- att . V : out[c][i], 2 chunks of 128 channels ----
    int wg = w >> 1;
    for (int cc = 0; cc < 2; cc++) {
        const bf16* vc = v_s + (size_t)cc * 128 * QP;

        float acc[4][4][4];
#pragma unroll
        for (int a = 0; a < 4; a++)
#pragma unroll
            for (int b = 0; b < 4; b++)
#pragma unroll
                for (int c = 0; c < 4; c++) acc[a][b][c] = 0.f;

#pragma unroll
        for (int ks = 0; ks < 8; ks++) {
            int k0 = ks * 16;
            u32 a[4][4], b[4][2];
            int ar  = ((l >> 3) & 1) * 8 + (l & 7);
            int acl = k0 + (l >> 4) * 8;
#pragma unroll
            for (int mf = 0; mf < 4; mf++)
                ldsm4(a[mf], smem_u32(vc + (m0 + mf * 16 + ar) * QP + acl));
            int brr = (l >> 4) * 8 + (l & 7);
            int bcl = k0 + ((l >> 3) & 1) * 8;
#pragma unroll
            for (int bi = 0; bi < 2; bi++) {
                u32 r4[4];
                ldsm4(r4, smem_u32(att_s + (n0 + bi * 16 + brr) * QP + bcl));
                b[bi * 2][0] = r4[0]; b[bi * 2][1] = r4[1];
                b[bi * 2 + 1][0] = r4[2]; b[bi * 2 + 1][1] = r4[3];
            }
#pragma unroll
            for (int mf = 0; mf < 4; mf++)
#pragma unroll
                for (int nf = 0; nf < 4; nf++)
                    mma_bf(acc[mf][nf], a[mf], b[nf]);
        }

        int g = l >> 2, tq = l & 3;
#pragma unroll
        for (int mf = 0; mf < 4; mf++) {
            float rs0 = 0.f, rs1 = 0.f, rm0 = -1e30f, rm1 = -1e30f;
#pragma unroll
            for (int nf = 0; nf < 4; nf++) {
                int i = n0 + nf * 8 + tq * 2;
                float2 iv = *(float2*)(inv_s + i);
                int c = m0 + mf * 16 + g;
                float o0 = acc[mf][nf][0] * iv.x;
                float o1 = acc[mf][nf][1] * iv.y;
                float o2 = acc[mf][nf][2] * iv.x;
                float o3 = acc[mf][nf][3] * iv.y;
                size_t b0 = (((size_t)n * CCH + cc * 128 + c) * HH + h) * (size_t)WW + i;
                size_t b1 = (((size_t)n * CCH + cc * 128 + c + 8) * HH + h) * (size_t)WW + i;
                *(u32*)(outb + b0) = packbf(o0, o1);
                *(u32*)(outb + b1) = packbf(o2, o3);
                rs0 += o0 + o1; rm0 = fmaxf(rm0, fmaxf(o0, o1));
                rs1 += o2 + o3; rm1 = fmaxf(rm1, fmaxf(o2, o3));
            }
#pragma unroll
            for (int off = 1; off < 4; off <<= 1) {
                rs0 += __shfl_xor_sync(0xffffffffu, rs0, off);
                rs1 += __shfl_xor_sync(0xffffffffu, rs1, off);
                rm0 = fmaxf(rm0, __shfl_xor_sync(0xffffffffu, rm0, off));
                rm1 = fmaxf(rm1, __shfl_xor_sync(0xffffffffu, rm1, off));
            }
            if (tq == 0) {
                int c128 = m0 + mf * 16 + g;
                psum[c128 * 4 + wg]       = rs0;
                psum[(c128 + 8) * 4 + wg] = rs1;
                pmax[c128 * 4 + wg]       = rm0;
                pmax[(c128 + 8) * 4 + wg] = rm1;
            }
        }
        __syncthreads();
        if (t < 128) {
            float s = psum[t * 4] + psum[t * 4 + 1] + psum[t * 4 + 2] + psum[t * 4 + 3];
            float m = fmaxf(fmaxf(pmax[t * 4], pmax[t * 4 + 1]),
                            fmaxf(pmax[t * 4 + 2], pmax[t * 4 + 3]));
            size_t nc = (size_t)n * CCH + cc * 128 + t;
            g_psum[nc * HH + h] = s;
            g_pmax[nc * HH + h] = m;
        }
        __syncthreads();
    }
}

// ---------------------------------------------------------------------------
__global__ void gate2(const float* __restrict__ W1, const float* __restrict__ W2)
{
    __shared__ float avg[CCH], mx[CCH], h1[2][16];
    int n = blockIdx.x, t = threadIdx.x;

    {
        const float4* ps = (const float4*)(g_psum + ((size_t)n * CCH + t) * HH);
        const float4* pm = (const float4*)(g_pmax + ((size_t)n * CCH + t) * HH);
        float s = 0.f, m = -1e30f;
#pragma unroll 8
        for (int q = 0; q < 32; q++) {
            float4 a = ps[q];
            s += a.x + a.y + a.z + a.w;
            float4 b = pm[q];
            m = fmaxf(m, fmaxf(fmaxf(b.x, b.y), fmaxf(b.z, b.w)));
        }
        avg[t] = s * (1.f / HWSZ);
        mx[t]  = m;
    }
    __syncthreads();

    {
        int dot = t >> 3, part = t & 7;
        int path = dot >> 4, r = dot & 15;
        const float* z  = path ? mx : avg;
        const float* wr = W1 + r * CCH + part * 32;
        float acc = 0.f;
#pragma unroll 8
        for (int c = 0; c < 32; c++) acc += wr[c] * z[part * 32 + c];
        acc += __shfl_xor_sync(0xffffffffu, acc, 1);
        acc += __shfl_xor_sync(0xffffffffu, acc, 2);
        acc += __shfl_xor_sync(0xffffffffu, acc, 4);
        if (part == 0) h1[path][r] = fmaxf(acc, 0.f);
    }
    __syncthreads();

    {
        float g = 0.f;
#pragma unroll
        for (int r = 0; r < 16; r++)
            g += W2[t * 16 + r] * (h1[0][r] + h1[1][r]);
        g_gate[n * CCH + t] = 1.f / (1.f + __expf(-g));
    }
}

__global__ void final_k(const float* __restrict__ x,
                        const float* __restrict__ gama,
                        float* __restrict__ o)
{
    size_t idx = (size_t)blockIdx.x * blockDim.x + threadIdx.x;
    float g = gama[0];
    uint2 av = ((const uint2*)g_attn)[idx];
    float4 xv = ((const float4*)x)[idx];
    float2 a0 = __bfloat1622float2(*(const __nv_bfloat162*)&av.x);
    float2 a1 = __bfloat1622float2(*(const __nv_bfloat162*)&av.y);
    float gt = g * g_gate[idx >> 12];
    float4 r;
    r.x = gt * a0.x + xv.x;
    r.y = gt * a0.y + xv.y;
    r.z = gt * a1.x + xv.z;
    r.w = gt * a1.y + xv.w;
    ((float4*)o)[idx] = r;
}

// ---------------------------------------------------------------------------
extern "C" void kernel_launch(void* const* d_in, const int* in_sizes, int n_in,
                              void* d_out, int out_size)
{
    const float* x    = (const float*)d_in[0];
    const float* Wq   = (const float*)d_in[1];
    const float* Wk   = (const float*)d_in[2];
    const float* Wv   = (const float*)d_in[3];
    const float* W1   = (const float*)d_in[4];
    const float* W2   = (const float*)d_in[5];
    const float* gama = (const float*)d_in[6];
    float* out = (float*)d_out;

    cudaFuncSetAttribute(fused_attn, cudaFuncAttributeMaxDynamicSharedMemorySize, SMEM_TOTAL);

    convert_w<<<48, 256>>>(Wq, Wk, Wv);
    fused_attn<<<NB * HH, 256, SMEM_TOTAL>>>(x);
    gate2<<<NB, 256>>>(W1, W2);
    final_k<<<(NB * CCH * HWSZ) / 1024, 256>>>(x, gama, out);
}

// round 14
// speedup vs baseline: 1.1079x; 1.1079x over previous
#include <cuda_runtime.h>
#include <cuda_bf16.h>
#include <math.h>

#define NB   8
#define CCH  256
#define HH   128
#define WW   128
#define HWSZ 16384
#define QKD  64

typedef unsigned int u32;
typedef __nv_bfloat16 bf16;

// ---------------- scratch ----------------
__device__ uint4 g_Wf[24 * 16 * 32];                    // W mma-fragment layout
__device__ __align__(16) bf16 g_attn[(size_t)NB * CCH * HWSZ];  // pre-gate out, bf16
__device__ float g_psum[(size_t)NB * CCH * HH];
__device__ float g_pmax[(size_t)NB * CCH * HH];
__device__ float g_gate[NB * CCH];

// ---------------- helpers ----------------
__device__ __forceinline__ u32 smem_u32(const void* p) {
    u32 a;
    asm("{.reg .u64 t; cvta.to.shared.u64 t, %1; cvt.u32.u64 %0, t;}"
        : "=r"(a) : "l"(p));
    return a;
}
__device__ __forceinline__ void ldsm4(u32* r, u32 a) {
    asm volatile("ldmatrix.sync.aligned.m8n8.x4.shared.b16 {%0,%1,%2,%3},[%4];"
        : "=r"(r[0]), "=r"(r[1]), "=r"(r[2]), "=r"(r[3]) : "r"(a));
}
__device__ __forceinline__ void ldsm4t(u32* r, u32 a) {
    asm volatile("ldmatrix.sync.aligned.m8n8.x4.trans.shared.b16 {%0,%1,%2,%3},[%4];"
        : "=r"(r[0]), "=r"(r[1]), "=r"(r[2]), "=r"(r[3]) : "r"(a));
}
__device__ __forceinline__ void mma_bf(float* d, const u32* a, const u32* b) {
    asm volatile(
        "mma.sync.aligned.m16n8k16.row.col.f32.bf16.bf16.f32 "
        "{%0,%1,%2,%3},{%4,%5,%6,%7},{%8,%9},{%0,%1,%2,%3};"
        : "+f"(d[0]), "+f"(d[1]), "+f"(d[2]), "+f"(d[3])
        : "r"(a[0]), "r"(a[1]), "r"(a[2]), "r"(a[3]), "r"(b[0]), "r"(b[1]));
}
__device__ __forceinline__ u32 packbf(float lo, float hi) {
    u32 r; asm("cvt.rn.bf16x2.f32 %0,%1,%2;" : "=r"(r) : "f"(hi), "f"(lo));
    return r;
}
__device__ __forceinline__ void cp16(u32 dst, const void* src) {
    asm volatile("cp.async.cg.shared.global [%0], [%1], 16;" :: "r"(dst), "l"(src));
}
#define CP_COMMIT() asm volatile("cp.async.commit_group;" ::: "memory")
#define CP_WAIT1()  asm volatile("cp.async.wait_group 1;" ::: "memory")

// ---------------------------------------------------------------------------
__global__ void convert_w(const float* __restrict__ Wq,
                          const float* __restrict__ Wk,
                          const float* __restrict__ Wv)
{
    int tid = blockIdx.x * 256 + threadIdx.x;   // 0..12287
    int mt  = tid >> 9;
    int rem = tid & 511;
    int kt  = rem >> 5;
    int l   = rem & 31;
    int g2 = l >> 2, tq2 = l & 3;
    int r0 = mt * 16 + g2;
    int c0 = kt * 16 + tq2 * 2;

    const float* S; int roff;
    if (r0 < 64)       { S = Wq; roff = r0; }
    else if (r0 < 128) { S = Wk; roff = r0 - 64; }
    else               { S = Wv; roff = r0 - 128; }
    const float* p0 = S + (size_t)roff * CCH;
    const float* p8 = p0 + 8 * CCH;

    uint4 o;
    o.x = packbf(p0[c0],     p0[c0 + 1]);
    o.y = packbf(p8[c0],     p8[c0 + 1]);
    o.z = packbf(p0[c0 + 8], p0[c0 + 9]);
    o.w = packbf(p8[c0 + 8], p8[c0 + 9]);
    g_Wf[tid] = o;
}

// ---------------------------------------------------------------------------
#define XT_PITCH 136
#define QP       136
#define SMEM_TOTAL 211456   // 178688 + 2*16384 staging

// dst[128][QP] = W-block(wt0) @ xt; 8 warps: m0=(w&1)*64 (mf 0..3), n0=(w>>1)*32
__device__ __forceinline__ void gemm_wx(int wt0, const bf16* xt, bf16* dst,
                                        int l, int m0, int n0)
{
    float acc[4][4][4];
#pragma unroll
    for (int a = 0; a < 4; a++)
#pragma unroll
        for (int b = 0; b < 4; b++)
#pragma unroll
            for (int c = 0; c < 4; c++) acc[a][b][c] = 0.f;

    int mt0 = wt0 + (m0 >> 4);
#pragma unroll
    for (int kt = 0; kt < 16; kt++) {
        u32 a[4][4], b[4][2];
#pragma unroll
        for (int mf = 0; mf < 4; mf++) {
            uint4 av = g_Wf[(size_t)((mt0 + mf) * 16 + kt) * 32 + l];
            a[mf][0] = av.x; a[mf][1] = av.y; a[mf][2] = av.z; a[mf][3] = av.w;
        }
        int kk = kt * 16;
        int br  = kk + ((l >> 3) & 1) * 8 + (l & 7);
        int bcl = (l >> 4) * 8;
#pragma unroll
        for (int bi = 0; bi < 2; bi++) {
            u32 r4[4];
            ldsm4t(r4, smem_u32(xt + br * XT_PITCH + n0 + bi * 16 + bcl));
            b[bi * 2][0] = r4[0]; b[bi * 2][1] = r4[1];
            b[bi * 2 + 1][0] = r4[2]; b[bi * 2 + 1][1] = r4[3];
        }
#pragma unroll
        for (int mf = 0; mf < 4; mf++)
#pragma unroll
            for (int nf = 0; nf < 4; nf++)
                mma_bf(acc[mf][nf], a[mf], b[nf]);
    }

    int g = l >> 2, tq = l & 3;
#pragma unroll
    for (int mf = 0; mf < 4; mf++)
#pragma unroll
        for (int nf = 0; nf < 4; nf++) {
            int col = n0 + nf * 8 + tq * 2;
            *(u32*)(dst + (m0 + mf * 16 + g) * QP + col)     = packbf(acc[mf][nf][0], acc[mf][nf][1]);
            *(u32*)(dst + (m0 + mf * 16 + g + 8) * QP + col) = packbf(acc[mf][nf][2], acc[mf][nf][3]);
        }
}

__global__ __launch_bounds__(256, 1) void fused_attn(const float* __restrict__ x)
{
    extern __shared__ char smc[];
    bf16*  xt    = (bf16*)smc;                  // [256][136] bf16
    bf16*  qk_s  = (bf16*)(smc + 69632);        // [128][136] bf16
    bf16*  att_s = qk_s;                        // overlay after logits
    bf16*  v_s   = (bf16*)(smc + 104448);       // [256][136] bf16
    float* psum  = (float*)(smc + 174080);      // [128][4]
    float* pmax  = psum + 512;                  // [128][4]
    float* inv_s = (float*)(smc + 178176);      // [128]
    float* xf32  = (float*)(smc + 178688);      // 2 x [32][128] fp32 staging

    bf16* outb = g_attn;

    int nh = blockIdx.x, n = nh >> 7, h = nh & 127;
    int t = threadIdx.x, l = t & 31, w = t >> 5;
    int m0 = (w & 1) * 64, n0 = (w >> 1) * 32;

    const float* xg = x + ((size_t)n * CCH * HH + h) * WW;
    u32 xf_base = smem_u32(xf32);

    // ---- prologue: issue chunks 0,1 ----
#pragma unroll
    for (int ch = 0; ch < 2; ch++) {
#pragma unroll
        for (int q = 0; q < 4; q++) {
            int e = t + q * 256;
            int c = e >> 5, i4 = (e & 31) << 2;
            cp16(xf_base + (ch & 1) * 16384 + (c * 128 + i4) * 4,
                 xg + ((size_t)(ch * 32 + c) * HWSZ) + i4);
        }
        CP_COMMIT();
    }

    // ---- pipelined x-convert + qk & v1 GEMMs fused (B frags shared) ----
    float acc2[2][4][4][4];
#pragma unroll
    for (int bk = 0; bk < 2; bk++)
#pragma unroll
        for (int a = 0; a < 4; a++)
#pragma unroll
            for (int b = 0; b < 4; b++)
#pragma unroll
                for (int c = 0; c < 4; c++) acc2[bk][a][b][c] = 0.f;

    int mt0 = (m0 >> 4);

#pragma unroll 1
    for (int ch = 0; ch < 8; ch++) {
        CP_WAIT1();
        __syncthreads();                         // chunk ch visible to all

        // convert staged fp32 -> bf16 xt rows [ch*32, ch*32+32)
        const float* src = xf32 + (ch & 1) * 4096;
#pragma unroll
        for (int q = 0; q < 4; q++) {
            int e = t + q * 256;
            int c = e >> 5, i4 = (e & 31) << 2;
            float4 v4 = *(const float4*)(src + c * 128 + i4);
            uint2 o;
            o.x = packbf(v4.x, v4.y);
            o.y = packbf(v4.z, v4.w);
            *(uint2*)(xt + (ch * 32 + c) * XT_PITCH + i4) = o;
        }
        __syncthreads();                         // buffer free + xt chunk ready

        if (ch < 6) {
#pragma unroll
            for (int q = 0; q < 4; q++) {
                int e = t + q * 256;
                int c = e >> 5, i4 = (e & 31) << 2;
                cp16(xf_base + (ch & 1) * 16384 + (c * 128 + i4) * 4,
                     xg + ((size_t)((ch + 2) * 32 + c) * HWSZ) + i4);
            }
            CP_COMMIT();
        }

        // fused qk+v1: 2 kt steps on this chunk, B frags shared by 2 A blocks
#pragma unroll
        for (int kt2 = 0; kt2 < 2; kt2++) {
            int kt = ch * 2 + kt2;
            int kk = kt * 16;
            u32 b[4][2];
            int br  = kk + ((l >> 3) & 1) * 8 + (l & 7);
            int bcl = (l >> 4) * 8;
#pragma unroll
            for (int bi = 0; bi < 2; bi++) {
                u32 r4[4];
                ldsm4t(r4, smem_u32(xt + br * XT_PITCH + n0 + bi * 16 + bcl));
                b[bi * 2][0] = r4[0]; b[bi * 2][1] = r4[1];
                b[bi * 2 + 1][0] = r4[2]; b[bi * 2 + 1][1] = r4[3];
            }
#pragma unroll
            for (int bk = 0; bk < 2; bk++) {
                int mtb = bk * 8 + mt0;
#pragma unroll
                for (int mf = 0; mf < 4; mf++) {
                    u32 a[4];
                    uint4 av = g_Wf[(size_t)((mtb + mf) * 16 + kt) * 32 + l];
                    a[0] = av.x; a[1] = av.y; a[2] = av.z; a[3] = av.w;
#pragma unroll
                    for (int nf = 0; nf < 4; nf++)
                        mma_bf(acc2[bk][mf][nf], a, b[nf]);
                }
            }
        }
    }

    // ---- epilogues: acc2 -> qk_s / v_s rows 0-127 ----
    {
        int g = l >> 2, tq = l & 3;
#pragma unroll
        for (int bk = 0; bk < 2; bk++) {
            bf16* dst = (bk == 0) ? qk_s : v_s;
#pragma unroll
            for (int mf = 0; mf < 4; mf++)
#pragma unroll
                for (int nf = 0; nf < 4; nf++) {
                    int col = n0 + nf * 8 + tq * 2;
                    *(u32*)(dst + (m0 + mf * 16 + g) * QP + col)     = packbf(acc2[bk][mf][nf][0], acc2[bk][mf][nf][1]);
                    *(u32*)(dst + (m0 + mf * 16 + g + 8) * QP + col) = packbf(acc2[bk][mf][nf][2], acc2[bk][mf][nf][3]);
                }
        }
    }

    // ---- v2 projection (xt fully resident) ----
    gemm_wx(16, xt, v_s + 128 * QP, l, m0, n0);
    __syncthreads();

    // ---- logits in registers + register softmax ----
    {
        float acc[4][4][4];
#pragma unroll
        for (int a = 0; a < 4; a++)
#pragma unroll
            for (int b = 0; b < 4; b++)
#pragma unroll
                for (int c = 0; c < 4; c++) acc[a][b][c] = 0.f;

        const bf16* k_s = qk_s + 64 * QP;
#pragma unroll
        for (int ks = 0; ks < 4; ks++) {
            int k0 = ks * 16;
            u32 a[4][4], b[4][2];
            int ar  = k0 + ((l >> 4) << 3) + (l & 7);
            int acl = ((l >> 3) & 1) * 8;
#pragma unroll
            for (int mf = 0; mf < 4; mf++)
                ldsm4t(a[mf], smem_u32(qk_s + ar * QP + m0 + mf * 16 + acl));
            int br  = k0 + ((l >> 3) & 1) * 8 + (l & 7);
            int bcl = (l >> 4) * 8;
#pragma unroll
            for (int bi = 0; bi < 2; bi++) {
                u32 r4[4];
                ldsm4t(r4, smem_u32(k_s + br * QP + n0 + bi * 16 + bcl));
                b[bi * 2][0] = r4[0]; b[bi * 2][1] = r4[1];
                b[bi * 2 + 1][0] = r4[2]; b[bi * 2 + 1][1] = r4[3];
            }
#pragma unroll
            for (int mf = 0; mf < 4; mf++)
#pragma unroll
                for (int nf = 0; nf < 4; nf++)
                    mma_bf(acc[mf][nf], a[mf], b[nf]);
        }

        int g = l >> 2, tq = l & 3, wj = w >> 1;

#pragma unroll
        for (int mf = 0; mf < 4; mf++) {
            float rl = -1e30f, rh = -1e30f;
#pragma unroll
            for (int nf = 0; nf < 4; nf++) {
                rl = fmaxf(rl, fmaxf(acc[mf][nf][0], acc[mf][nf][1]));
                rh = fmaxf(rh, fmaxf(acc[mf][nf][2], acc[mf][nf][3]));
            }
            rl = fmaxf(rl, __shfl_xor_sync(0xffffffffu, rl, 1));
            rl = fmaxf(rl, __shfl_xor_sync(0xffffffffu, rl, 2));
            rh = fmaxf(rh, __shfl_xor_sync(0xffffffffu, rh, 1));
            rh = fmaxf(rh, __shfl_xor_sync(0xffffffffu, rh, 2));
            if (tq == 0) {
                pmax[(m0 + mf * 16 + g) * 4 + wj]     = rl;
                pmax[(m0 + mf * 16 + g + 8) * 4 + wj] = rh;
            }
        }
        __syncthreads();   // max partials visible; ALL qk ldsm reads complete

#pragma unroll
        for (int mf = 0; mf < 4; mf++) {
            int il = m0 + mf * 16 + g, ih = il + 8;
            float Ml = fmaxf(fmaxf(pmax[il * 4], pmax[il * 4 + 1]),
                             fmaxf(pmax[il * 4 + 2], pmax[il * 4 + 3]));
            float Mh = fmaxf(fmaxf(pmax[ih * 4], pmax[ih * 4 + 1]),
                             fmaxf(pmax[ih * 4 + 2], pmax[ih * 4 + 3]));
            float sl = 0.f, sh = 0.f;
#pragma unroll
            for (int nf = 0; nf < 4; nf++) {
                float e0 = __expf(acc[mf][nf][0] - Ml);
                float e1 = __expf(acc[mf][nf][1] - Ml);
                float e2 = __expf(acc[mf][nf][2] - Mh);
                float e3 = __expf(acc[mf][nf][3] - Mh);
                sl += e0 + e1; sh += e2 + e3;
                int j = n0 + nf * 8 + tq * 2;
                *(u32*)(att_s + il * QP + j) = packbf(e0, e1);
                *(u32*)(att_s + ih * QP + j) = packbf(e2, e3);
            }
            sl += __shfl_xor_sync(0xffffffffu, sl, 1);
            sl += __shfl_xor_sync(0xffffffffu, sl, 2);
            sh += __shfl_xor_sync(0xffffffffu, sh, 1);
            sh += __shfl_xor_sync(0xffffffffu, sh, 2);
            if (tq == 0) {
                psum[il * 4 + wj] = sl;
                psum[ih * 4 + wj] = sh;
            }
        }
        __syncthreads();

        if (t < 128)
            inv_s[t] = 1.f / (psum[t * 4] + psum[t * 4 + 1] + psum[t * 4 + 2] + psum[t * 4 + 3]);
        __syncthreads();
    }

    // ---- att . V : out[c][i], 2 chunks of 128 channels ----
    int wg = w >> 1;
    for (int cc = 0; cc < 2; cc++) {
        const bf16* vc = v_s + (size_t)cc * 128 * QP;

        float acc[4][4][4];
#pragma unroll
        for (int a = 0; a < 4; a++)
#pragma unroll
            for (int b = 0; b < 4; b++)
#pragma unroll
                for (int c = 0; c < 4; c++) acc[a][b][c] = 0.f;

#pragma unroll
        for (int ks = 0; ks < 8; ks++) {
            int k0 = ks * 16;
            u32 a[4][4], b[4][2];
            int ar  = ((l >> 3) & 1) * 8 + (l & 7);
            int acl = k0 + (l >> 4) * 8;
#pragma unroll
            for (int mf = 0; mf < 4; mf++)
                ldsm4(a[mf], smem_u32(vc + (m0 + mf * 16 + ar) * QP + acl));
            int brr = (l >> 4) * 8 + (l & 7);
            int bcl = k0 + ((l >> 3) & 1) * 8;
#pragma unroll
            for (int bi = 0; bi < 2; bi++) {
                u32 r4[4];
                ldsm4(r4, smem_u32(att_s + (n0 + bi * 16 + brr) * QP + bcl));
                b[bi * 2][0] = r4[0]; b[bi * 2][1] = r4[1];
                b[bi * 2 + 1][0] = r4[2]; b[bi * 2 + 1][1] = r4[3];
            }
#pragma unroll
            for (int mf = 0; mf < 4; mf++)
#pragma unroll
                for (int nf = 0; nf < 4; nf++)
                    mma_bf(acc[mf][nf], a[mf], b[nf]);
        }

        int g = l >> 2, tq = l & 3;
#pragma unroll
        for (int mf = 0; mf < 4; mf++) {
            float rs0 = 0.f, rs1 = 0.f, rm0 = -1e30f, rm1 = -1e30f;
#pragma unroll
            for (int nf = 0; nf < 4; nf++) {
                int i = n0 + nf * 8 + tq * 2;
                float2 iv = *(float2*)(inv_s + i);
                int c = m0 + mf * 16 + g;
                float o0 = acc[mf][nf][0] * iv.x;
                float o1 = acc[mf][nf][1] * iv.y;
                float o2 = acc[mf][nf][2] * iv.x;
                float o3 = acc[mf][nf][3] * iv.y;
                size_t b0 = (((size_t)n * CCH + cc * 128 + c) * HH + h) * (size_t)WW + i;
                size_t b1 = (((size_t)n * CCH + cc * 128 + c + 8) * HH + h) * (size_t)WW + i;
                *(u32*)(outb + b0) = packbf(o0, o1);
                *(u32*)(outb + b1) = packbf(o2, o3);
                rs0 += o0 + o1; rm0 = fmaxf(rm0, fmaxf(o0, o1));
                rs1 += o2 + o3; rm1 = fmaxf(rm1, fmaxf(o2, o3));
            }
#pragma unroll
            for (int off = 1; off < 4; off <<= 1) {
                rs0 += __shfl_xor_sync(0xffffffffu, rs0, off);
                rs1 += __shfl_xor_sync(0xffffffffu, rs1, off);
                rm0 = fmaxf(rm0, __shfl_xor_sync(0xffffffffu, rm0, off));
                rm1 = fmaxf(rm1, __shfl_xor_sync(0xffffffffu, rm1, off));
            }
            if (tq == 0) {
                int c128 = m0 + mf * 16 + g;
                psum[c128 * 4 + wg]       = rs0;
                psum[(c128 + 8) * 4 + wg] = rs1;
                pmax[c128 * 4 + wg]       = rm0;
                pmax[(c128 + 8) * 4 + wg] = rm1;
            }
        }
        __syncthreads();
        if (t < 128) {
            float s = psum[t * 4] + psum[t * 4 + 1] + psum[t * 4 + 2] + psum[t * 4 + 3];
            float m = fmaxf(fmaxf(pmax[t * 4], pmax[t * 4 + 1]),
                            fmaxf(pmax[t * 4 + 2], pmax[t * 4 + 3]));
            size_t nc = (size_t)n * CCH + cc * 128 + t;
            g_psum[nc * HH + h] = s;
            g_pmax[nc * HH + h] = m;
        }
        __syncthreads();
    }
}

// ---------------------------------------------------------------------------
__global__ void gate2(const float* __restrict__ W1, const float* __restrict__ W2)
{
    __shared__ float avg[CCH], mx[CCH], h1[2][16];
    int n = blockIdx.x, t = threadIdx.x;

    {
        const float4* ps = (const float4*)(g_psum + ((size_t)n * CCH + t) * HH);
        const float4* pm = (const float4*)(g_pmax + ((size_t)n * CCH + t) * HH);
        float s = 0.f, m = -1e30f;
#pragma unroll 8
        for (int q = 0; q < 32; q++) {
            float4 a = ps[q];
            s += a.x + a.y + a.z + a.w;
            float4 b = pm[q];
            m = fmaxf(m, fmaxf(fmaxf(b.x, b.y), fmaxf(b.z, b.w)));
        }
        avg[t] = s * (1.f / HWSZ);
        mx[t]  = m;
    }
    __syncthreads();

    {
        int dot = t >> 3, part = t & 7;
        int path = dot >> 4, r = dot & 15;
        const float* z  = path ? mx : avg;
        const float* wr = W1 + r * CCH + part * 32;
        float acc = 0.f;
#pragma unroll 8
        for (int c = 0; c < 32; c++) acc += wr[c] * z[part * 32 + c];
        acc += __shfl_xor_sync(0xffffffffu, acc, 1);
        acc += __shfl_xor_sync(0xffffffffu, acc, 2);
        acc += __shfl_xor_sync(0xffffffffu, acc, 4);
        if (part == 0) h1[path][r] = fmaxf(acc, 0.f);
    }
    __syncthreads();

    {
        float g = 0.f;
#pragma unroll
        for (int r = 0; r < 16; r++)
            g += W2[t * 16 + r] * (h1[0][r] + h1[1][r]);
        g_gate[n * CCH + t] = 1.f / (1.f + __expf(-g));
    }
}

__global__ void final_k(const float* __restrict__ x,
                        const float* __restrict__ gama,
                        float* __restrict__ o)
{
    size_t idx = (size_t)blockIdx.x * blockDim.x + threadIdx.x;
    float g = gama[0];
    uint2 av = ((const uint2*)g_attn)[idx];
    float4 xv = ((const float4*)x)[idx];
    float2 a0 = __bfloat1622float2(*(const __nv_bfloat162*)&av.x);
    float2 a1 = __bfloat1622float2(*(const __nv_bfloat162*)&av.y);
    float gt = g * g_gate[idx >> 12];
    float4 r;
    r.x = gt * a0.x + xv.x;
    r.y = gt * a0.y + xv.y;
    r.z = gt * a1.x + xv.z;
    r.w = gt * a1.y + xv.w;
    ((float4*)o)[idx] = r;
}

// ---------------------------------------------------------------------------
extern "C" void kernel_launch(void* const* d_in, const int* in_sizes, int n_in,
                              void* d_out, int out_size)
{
    const float* x    = (const float*)d_in[0];
    const float* Wq   = (const float*)d_in[1];
    const float* Wk   = (const float*)d_in[2];
    const float* Wv   = (const float*)d_in[3];
    const float* W1   = (const float*)d_in[4];
    const float* W2   = (const float*)d_in[5];
    const float* gama = (const float*)d_in[6];
    float* out = (float*)d_out;

    cudaFuncSetAttribute(fused_attn, cudaFuncAttributeMaxDynamicSharedMemorySize, SMEM_TOTAL);

    convert_w<<<48, 256>>>(Wq, Wk, Wv);
    fused_attn<<<NB * HH, 256, SMEM_TOTAL>>>(x);
    gate2<<<NB, 256>>>(W1, W2);
    final_k<<<(NB * CCH * HWSZ) / 1024, 256>>>(x, gama, out);
}

// round 15
// speedup vs baseline: 1.1652x; 1.0517x over previous
#include <cuda_runtime.h>
#include <cuda_bf16.h>
#include <math.h>

#define NB   8
#define CCH  256
#define HH   128
#define WW   128
#define HWSZ 16384
#define QKD  64

typedef unsigned int u32;
typedef __nv_bfloat16 bf16;

// ---------------- scratch ----------------
__device__ uint4 g_Wf[24 * 16 * 32];                    // W mma-fragment layout
__device__ __align__(16) bf16 g_attn[(size_t)NB * CCH * HWSZ];  // pre-gate out, bf16
__device__ float g_psum[(size_t)NB * CCH * HH];
__device__ float g_pmax[(size_t)NB * CCH * HH];
__device__ float g_gate[NB * CCH];

// ---------------- helpers ----------------
__device__ __forceinline__ u32 smem_u32(const void* p) {
    u32 a;
    asm("{.reg .u64 t; cvta.to.shared.u64 t, %1; cvt.u32.u64 %0, t;}"
        : "=r"(a) : "l"(p));
    return a;
}
__device__ __forceinline__ void ldsm4(u32* r, u32 a) {
    asm volatile("ldmatrix.sync.aligned.m8n8.x4.shared.b16 {%0,%1,%2,%3},[%4];"
        : "=r"(r[0]), "=r"(r[1]), "=r"(r[2]), "=r"(r[3]) : "r"(a));
}
__device__ __forceinline__ void ldsm4t(u32* r, u32 a) {
    asm volatile("ldmatrix.sync.aligned.m8n8.x4.trans.shared.b16 {%0,%1,%2,%3},[%4];"
        : "=r"(r[0]), "=r"(r[1]), "=r"(r[2]), "=r"(r[3]) : "r"(a));
}
__device__ __forceinline__ void mma_bf(float* d, const u32* a, const u32* b) {
    asm volatile(
        "mma.sync.aligned.m16n8k16.row.col.f32.bf16.bf16.f32 "
        "{%0,%1,%2,%3},{%4,%5,%6,%7},{%8,%9},{%0,%1,%2,%3};"
        : "+f"(d[0]), "+f"(d[1]), "+f"(d[2]), "+f"(d[3])
        : "r"(a[0]), "r"(a[1]), "r"(a[2]), "r"(a[3]), "r"(b[0]), "r"(b[1]));
}
__device__ __forceinline__ u32 packbf(float lo, float hi) {
    u32 r; asm("cvt.rn.bf16x2.f32 %0,%1,%2;" : "=r"(r) : "f"(hi), "f"(lo));
    return r;
}
__device__ __forceinline__ void cp16(u32 dst, const void* src) {
    asm volatile("cp.async.cg.shared.global [%0], [%1], 16;" :: "r"(dst), "l"(src));
}
#define CP_COMMIT() asm volatile("cp.async.commit_group;" ::: "memory")
#define CP_WAIT1()  asm volatile("cp.async.wait_group 1;" ::: "memory")

// ---------------------------------------------------------------------------
__global__ void convert_w(const float* __restrict__ Wq,
                          const float* __restrict__ Wk,
                          const float* __restrict__ Wv)
{
    int tid = blockIdx.x * 256 + threadIdx.x;   // 0..12287
    int mt  = tid >> 9;
    int rem = tid & 511;
    int kt  = rem >> 5;
    int l   = rem & 31;
    int g2 = l >> 2, tq2 = l & 3;
    int r0 = mt * 16 + g2;
    int c0 = kt * 16 + tq2 * 2;

    const float* S; int roff;
    if (r0 < 64)       { S = Wq; roff = r0; }
    else if (r0 < 128) { S = Wk; roff = r0 - 64; }
    else               { S = Wv; roff = r0 - 128; }
    const float* p0 = S + (size_t)roff * CCH;
    const float* p8 = p0 + 8 * CCH;

    uint4 o;
    o.x = packbf(p0[c0],     p0[c0 + 1]);
    o.y = packbf(p8[c0],     p8[c0 + 1]);
    o.z = packbf(p0[c0 + 8], p0[c0 + 9]);
    o.w = packbf(p8[c0 + 8], p8[c0 + 9]);
    g_Wf[tid] = o;
}

// ---------------------------------------------------------------------------
#define XT_PITCH 136
#define QP       136
#define SMEM_TOTAL 211456   // 178688 + 2*16384 staging

// dst[128][QP] = W-block(wt0) @ xt; 8 warps: m0=(w&1)*64 (mf 0..3), n0=(w>>1)*32
__device__ __forceinline__ void gemm_wx(int wt0, const bf16* xt, bf16* dst,
                                        int l, int m0, int n0)
{
    float acc[4][4][4];
#pragma unroll
    for (int a = 0; a < 4; a++)
#pragma unroll
        for (int b = 0; b < 4; b++)
#pragma unroll
            for (int c = 0; c < 4; c++) acc[a][b][c] = 0.f;

    int mt0 = wt0 + (m0 >> 4);
#pragma unroll
    for (int kt = 0; kt < 16; kt++) {
        u32 a[4][4], b[4][2];
#pragma unroll
        for (int mf = 0; mf < 4; mf++) {
            uint4 av = g_Wf[(size_t)((mt0 + mf) * 16 + kt) * 32 + l];
            a[mf][0] = av.x; a[mf][1] = av.y; a[mf][2] = av.z; a[mf][3] = av.w;
        }
        int kk = kt * 16;
        int br  = kk + ((l >> 3) & 1) * 8 + (l & 7);
        int bcl = (l >> 4) * 8;
#pragma unroll
        for (int bi = 0; bi < 2; bi++) {
            u32 r4[4];
            ldsm4t(r4, smem_u32(xt + br * XT_PITCH + n0 + bi * 16 + bcl));
            b[bi * 2][0] = r4[0]; b[bi * 2][1] = r4[1];
            b[bi * 2 + 1][0] = r4[2]; b[bi * 2 + 1][1] = r4[3];
        }
#pragma unroll
        for (int mf = 0; mf < 4; mf++)
#pragma unroll
            for (int nf = 0; nf < 4; nf++)
                mma_bf(acc[mf][nf], a[mf], b[nf]);
    }

    int g = l >> 2, tq = l & 3;
#pragma unroll
    for (int mf = 0; mf < 4; mf++)
#pragma unroll
        for (int nf = 0; nf < 4; nf++) {
            int col = n0 + nf * 8 + tq * 2;
            *(u32*)(dst + (m0 + mf * 16 + g) * QP + col)     = packbf(acc[mf][nf][0], acc[mf][nf][1]);
            *(u32*)(dst + (m0 + mf * 16 + g + 8) * QP + col) = packbf(acc[mf][nf][2], acc[mf][nf][3]);
        }
}

__global__ __launch_bounds__(256, 1) void fused_attn(const float* __restrict__ x)
{
    extern __shared__ char smc[];
    bf16*  xt    = (bf16*)smc;                  // [256][136] bf16
    bf16*  stage = (bf16*)smc;                  // att.V output stage (overlays dead xt)
    bf16*  qk_s  = (bf16*)(smc + 69632);        // [128][136] bf16
    bf16*  att_s = qk_s;                        // overlay after logits
    bf16*  v_s   = (bf16*)(smc + 104448);       // [256][136] bf16
    float* psum  = (float*)(smc + 174080);      // [128][4]
    float* pmax  = psum + 512;                  // [128][4]
    float* inv_s = (float*)(smc + 178176);      // [128]
    float* xf32  = (float*)(smc + 178688);      // 2 x [32][128] fp32 staging

    bf16* outb = g_attn;

    int nh = blockIdx.x, n = nh >> 7, h = nh & 127;
    int t = threadIdx.x, l = t & 31, w = t >> 5;
    int m0 = (w & 1) * 64, n0 = (w >> 1) * 32;

    const float* xg = x + ((size_t)n * CCH * HH + h) * WW;
    u32 xf_base = smem_u32(xf32);

    // ---- prologue: issue chunks 0,1 ----
#pragma unroll
    for (int ch = 0; ch < 2; ch++) {
#pragma unroll
        for (int q = 0; q < 4; q++) {
            int e = t + q * 256;
            int c = e >> 5, i4 = (e & 31) << 2;
            cp16(xf_base + (ch & 1) * 16384 + (c * 128 + i4) * 4,
                 xg + ((size_t)(ch * 32 + c) * HWSZ) + i4);
        }
        CP_COMMIT();
    }

    // ---- pipelined x-convert + qk GEMM ----
    float accq[4][4][4];
#pragma unroll
    for (int a = 0; a < 4; a++)
#pragma unroll
        for (int b = 0; b < 4; b++)
#pragma unroll
            for (int c = 0; c < 4; c++) accq[a][b][c] = 0.f;

    int mt0q = (m0 >> 4);

#pragma unroll 1
    for (int ch = 0; ch < 8; ch++) {
        CP_WAIT1();
        __syncthreads();                         // chunk ch visible to all

        const float* src = xf32 + (ch & 1) * 4096;
#pragma unroll
        for (int q = 0; q < 4; q++) {
            int e = t + q * 256;
            int c = e >> 5, i4 = (e & 31) << 2;
            float4 v4 = *(const float4*)(src + c * 128 + i4);
            uint2 o;
            o.x = packbf(v4.x, v4.y);
            o.y = packbf(v4.z, v4.w);
            *(uint2*)(xt + (ch * 32 + c) * XT_PITCH + i4) = o;
        }
        __syncthreads();                         // buffer free + xt chunk ready

        if (ch < 6) {
#pragma unroll
            for (int q = 0; q < 4; q++) {
                int e = t + q * 256;
                int c = e >> 5, i4 = (e & 31) << 2;
                cp16(xf_base + (ch & 1) * 16384 + (c * 128 + i4) * 4,
                     xg + ((size_t)((ch + 2) * 32 + c) * HWSZ) + i4);
            }
            CP_COMMIT();
        }

        // qk GEMM: 2 kt steps on this chunk
#pragma unroll
        for (int kt2 = 0; kt2 < 2; kt2++) {
            int kt = ch * 2 + kt2;
            u32 a[4][4], b[4][2];
#pragma unroll
            for (int mf = 0; mf < 4; mf++) {
                uint4 av = g_Wf[(size_t)((mt0q + mf) * 16 + kt) * 32 + l];
                a[mf][0] = av.x; a[mf][1] = av.y; a[mf][2] = av.z; a[mf][3] = av.w;
            }
            int kk = kt * 16;
            int br  = kk + ((l >> 3) & 1) * 8 + (l & 7);
            int bcl = (l >> 4) * 8;
#pragma unroll
            for (int bi = 0; bi < 2; bi++) {
                u32 r4[4];
                ldsm4t(r4, smem_u32(xt + br * XT_PITCH + n0 + bi * 16 + bcl));
                b[bi * 2][0] = r4[0]; b[bi * 2][1] = r4[1];
                b[bi * 2 + 1][0] = r4[2]; b[bi * 2 + 1][1] = r4[3];
            }
#pragma unroll
            for (int mf = 0; mf < 4; mf++)
#pragma unroll
                for (int nf = 0; nf < 4; nf++)
                    mma_bf(accq[mf][nf], a[mf], b[nf]);
        }
    }

    // qk epilogue -> qk_s
    {
        int g = l >> 2, tq = l & 3;
#pragma unroll
        for (int mf = 0; mf < 4; mf++)
#pragma unroll
            for (int nf = 0; nf < 4; nf++) {
                int col = n0 + nf * 8 + tq * 2;
                *(u32*)(qk_s + (m0 + mf * 16 + g) * QP + col)     = packbf(accq[mf][nf][0], accq[mf][nf][1]);
                *(u32*)(qk_s + (m0 + mf * 16 + g + 8) * QP + col) = packbf(accq[mf][nf][2], accq[mf][nf][3]);
            }
    }

    // ---- v projections (xt fully resident) ----
    gemm_wx(8,  xt, v_s,            l, m0, n0);
    gemm_wx(16, xt, v_s + 128 * QP, l, m0, n0);
    __syncthreads();

    // ---- logits in registers + register softmax ----
    {
        float acc[4][4][4];
#pragma unroll
        for (int a = 0; a < 4; a++)
#pragma unroll
            for (int b = 0; b < 4; b++)
#pragma unroll
                for (int c = 0; c < 4; c++) acc[a][b][c] = 0.f;

        const bf16* k_s = qk_s + 64 * QP;
#pragma unroll
        for (int ks = 0; ks < 4; ks++) {
            int k0 = ks * 16;
            u32 a[4][4], b[4][2];
            int ar  = k0 + ((l >> 4) << 3) + (l & 7);
            int acl = ((l >> 3) & 1) * 8;
#pragma unroll
            for (int mf = 0; mf < 4; mf++)
                ldsm4t(a[mf], smem_u32(qk_s + ar * QP + m0 + mf * 16 + acl));
            int br  = k0 + ((l >> 3) & 1) * 8 + (l & 7);
            int bcl = (l >> 4) * 8;
#pragma unroll
            for (int bi = 0; bi < 2; bi++) {
                u32 r4[4];
                ldsm4t(r4, smem_u32(k_s + br * QP + n0 + bi * 16 + bcl));
                b[bi * 2][0] = r4[0]; b[bi * 2][1] = r4[1];
                b[bi * 2 + 1][0] = r4[2]; b[bi * 2 + 1][1] = r4[3];
            }
#pragma unroll
            for (int mf = 0; mf < 4; mf++)
#pragma unroll
                for (int nf = 0; nf < 4; nf++)
                    mma_bf(acc[mf][nf], a[mf], b[nf]);
        }

        int g = l >> 2, tq = l & 3, wj = w >> 1;

#pragma unroll
        for (int mf = 0; mf < 4; mf++) {
            float rl = -1e30f, rh = -1e30f;
#pragma unroll
            for (int nf = 0; nf < 4; nf++) {
                rl = fmaxf(rl, fmaxf(acc[mf][nf][0], acc[mf][nf][1]));
                rh = fmaxf(rh, fmaxf(acc[mf][nf][2], acc[mf][nf][3]));
            }
            rl = fmaxf(rl, __shfl_xor_sync(0xffffffffu, rl, 1));
            rl = fmaxf(rl, __shfl_xor_sync(0xffffffffu, rl, 2));
            rh = fmaxf(rh, __shfl_xor_sync(0xffffffffu, rh, 1));
            rh = fmaxf(rh, __shfl_xor_sync(0xffffffffu, rh, 2));
            if (tq == 0) {
                pmax[(m0 + mf * 16 + g) * 4 + wj]     = rl;
                pmax[(m0 + mf * 16 + g + 8) * 4 + wj] = rh;
            }
        }
        __syncthreads();   // max partials visible; ALL qk ldsm reads complete

#pragma unroll
        for (int mf = 0; mf < 4; mf++) {
            int il = m0 + mf * 16 + g, ih = il + 8;
            float Ml = fmaxf(fmaxf(pmax[il * 4], pmax[il * 4 + 1]),
                             fmaxf(pmax[il * 4 + 2], pmax[il * 4 + 3]));
            float Mh = fmaxf(fmaxf(pmax[ih * 4], pmax[ih * 4 + 1]),
                             fmaxf(pmax[ih * 4 + 2], pmax[ih * 4 + 3]));
            float sl = 0.f, sh = 0.f;
#pragma unroll
            for (int nf = 0; nf < 4; nf++) {
                float e0 = __expf(acc[mf][nf][0] - Ml);
                float e1 = __expf(acc[mf][nf][1] - Ml);
                float e2 = __expf(acc[mf][nf][2] - Mh);
                float e3 = __expf(acc[mf][nf][3] - Mh);
                sl += e0 + e1; sh += e2 + e3;
                int j = n0 + nf * 8 + tq * 2;
                *(u32*)(att_s + il * QP + j) = packbf(e0, e1);
                *(u32*)(att_s + ih * QP + j) = packbf(e2, e3);
            }
            sl += __shfl_xor_sync(0xffffffffu, sl, 1);
            sl += __shfl_xor_sync(0xffffffffu, sl, 2);
            sh += __shfl_xor_sync(0xffffffffu, sh, 1);
            sh += __shfl_xor_sync(0xffffffffu, sh, 2);
            if (tq == 0) {
                psum[il * 4 + wj] = sl;
                psum[ih * 4 + wj] = sh;
            }
        }
        __syncthreads();

        if (t < 128)
            inv_s[t] = 1.f / (psum[t * 4] + psum[t * 4 + 1] + psum[t * 4 + 2] + psum[t * 4 + 3]);
        __syncthreads();
    }

    // ---- att . V : out[c][i], 2 chunks of 128 channels ----
    int wg = w >> 1;
    for (int cc = 0; cc < 2; cc++) {
        const bf16* vc = v_s + (size_t)cc * 128 * QP;

        float acc[4][4][4];
#pragma unroll
        for (int a = 0; a < 4; a++)
#pragma unroll
            for (int b = 0; b < 4; b++)
#pragma unroll
                for (int c = 0; c < 4; c++) acc[a][b][c] = 0.f;

#pragma unroll
        for (int ks = 0; ks < 8; ks++) {
            int k0 = ks * 16;
            u32 a[4][4], b[4][2];
            int ar  = ((l >> 3) & 1) * 8 + (l & 7);
            int acl = k0 + (l >> 4) * 8;
#pragma unroll
            for (int mf = 0; mf < 4; mf++)
                ldsm4(a[mf], smem_u32(vc + (m0 + mf * 16 + ar) * QP + acl));
            int brr = (l >> 4) * 8 + (l & 7);
            int bcl = k0 + ((l >> 3) & 1) * 8;
#pragma unroll
            for (int bi = 0; bi < 2; bi++) {
                u32 r4[4];
                ldsm4(r4, smem_u32(att_s + (n0 + bi * 16 + brr) * QP + bcl));
                b[bi * 2][0] = r4[0]; b[bi * 2][1] = r4[1];
                b[bi * 2 + 1][0] = r4[2]; b[bi * 2 + 1][1] = r4[3];
            }
#pragma unroll
            for (int mf = 0; mf < 4; mf++)
#pragma unroll
                for (int nf = 0; nf < 4; nf++)
                    mma_bf(acc[mf][nf], a[mf], b[nf]);
        }

        // epilogue: scale, stage to smem (dead xt region), reduce partials
        int g = l >> 2, tq = l & 3;
#pragma unroll
        for (int mf = 0; mf < 4; mf++) {
            float rs0 = 0.f, rs1 = 0.f, rm0 = -1e30f, rm1 = -1e30f;
#pragma unroll
            for (int nf = 0; nf < 4; nf++) {
                int i = n0 + nf * 8 + tq * 2;
                float2 iv = *(float2*)(inv_s + i);
                int c = m0 + mf * 16 + g;
                float o0 = acc[mf][nf][0] * iv.x;
                float o1 = acc[mf][nf][1] * iv.y;
                float o2 = acc[mf][nf][2] * iv.x;
                float o3 = acc[mf][nf][3] * iv.y;
                *(u32*)(stage + c * QP + i)       = packbf(o0, o1);
                *(u32*)(stage + (c + 8) * QP + i) = packbf(o2, o3);
                rs0 += o0 + o1; rm0 = fmaxf(rm0, fmaxf(o0, o1));
                rs1 += o2 + o3; rm1 = fmaxf(rm1, fmaxf(o2, o3));
            }
#pragma unroll
            for (int off = 1; off < 4; off <<= 1) {
                rs0 += __shfl_xor_sync(0xffffffffu, rs0, off);
                rs1 += __shfl_xor_sync(0xffffffffu, rs1, off);
                rm0 = fmaxf(rm0, __shfl_xor_sync(0xffffffffu, rm0, off));
                rm1 = fmaxf(rm1, __shfl_xor_sync(0xffffffffu, rm1, off));
            }
            if (tq == 0) {
                int c128 = m0 + mf * 16 + g;
                psum[c128 * 4 + wg]       = rs0;
                psum[(c128 + 8) * 4 + wg] = rs1;
                pmax[c128 * 4 + wg]       = rm0;
                pmax[(c128 + 8) * 4 + wg] = rm1;
            }
        }
        __syncthreads();   // stage + partials visible

        // coalesced gmem write: 128 rows x 128 i bf16, 16B per thread-slot
#pragma unroll
        for (int q = 0; q < 8; q++) {
            int e = t + q * 256;                // 0..2047
            int row = e >> 4, c8 = (e & 15) * 8;
            uint4 vv = *(const uint4*)(stage + row * QP + c8);
            size_t dst = (((size_t)n * CCH + cc * 128 + row) * HH + h) * (size_t)WW + c8;
            *(uint4*)(outb + dst) = vv;
        }
        if (t < 128) {
            float s = psum[t * 4] + psum[t * 4 + 1] + psum[t * 4 + 2] + psum[t * 4 + 3];
            float m = fmaxf(fmaxf(pmax[t * 4], pmax[t * 4 + 1]),
                            fmaxf(pmax[t * 4 + 2], pmax[t * 4 + 3]));
            size_t nc = (size_t)n * CCH + cc * 128 + t;
            g_psum[nc * HH + h] = s;
            g_pmax[nc * HH + h] = m;
        }
        __syncthreads();   // stage reusable for next cc
    }
}

// ---------------------------------------------------------------------------
__global__ void gate2(const float* __restrict__ W1, const float* __restrict__ W2)
{
    __shared__ float avg[CCH], mx[CCH], h1[2][16];
    int n = blockIdx.x, t = threadIdx.x;

    {
        const float4* ps = (const float4*)(g_psum + ((size_t)n * CCH + t) * HH);
        const float4* pm = (const float4*)(g_pmax + ((size_t)n * CCH + t) * HH);
        float s = 0.f, m = -1e30f;
#pragma unroll 8
        for (int q = 0; q < 32; q++) {
            float4 a = ps[q];
            s += a.x + a.y + a.z + a.w;
            float4 b = pm[q];
            m = fmaxf(m, fmaxf(fmaxf(b.x, b.y), fmaxf(b.z, b.w)));
        }
        avg[t] = s * (1.f / HWSZ);
        mx[t]  = m;
    }
    __syncthreads();

    {
        int dot = t >> 3, part = t & 7;
        int path = dot >> 4, r = dot & 15;
        const float* z  = path ? mx : avg;
        const float* wr = W1 + r * CCH + part * 32;
        float acc = 0.f;
#pragma unroll 8
        for (int c = 0; c < 32; c++) acc += wr[c] * z[part * 32 + c];
        acc += __shfl_xor_sync(0xffffffffu, acc, 1);
        acc += __shfl_xor_sync(0xffffffffu, acc, 2);
        acc += __shfl_xor_sync(0xffffffffu, acc, 4);
        if (part == 0) h1[path][r] = fmaxf(acc, 0.f);
    }
    __syncthreads();

    {
        float g = 0.f;
#pragma unroll
        for (int r = 0; r < 16; r++)
            g += W2[t * 16 + r] * (h1[0][r] + h1[1][r]);
        g_gate[n * CCH + t] = 1.f / (1.f + __expf(-g));
    }
}

__global__ void final_k(const float* __restrict__ x,
                        const float* __restrict__ gama,
                        float* __restrict__ o)
{
    size_t idx = (size_t)blockIdx.x * blockDim.x + threadIdx.x;   // per 8 elements
    float g = gama[0];
    uint4 av = ((const uint4*)g_attn)[idx];
    float4 xv0 = ((const float4*)x)[2 * idx];
    float4 xv1 = ((const float4*)x)[2 * idx + 1];
    float2 a0 = __bfloat1622float2(*(const __nv_bfloat162*)&av.x);
    float2 a1 = __bfloat1622float2(*(const __nv_bfloat162*)&av.y);
    float2 a2 = __bfloat1622float2(*(const __nv_bfloat162*)&av.z);
    float2 a3 = __bfloat1622float2(*(const __nv_bfloat162*)&av.w);
    float gt = g * g_gate[idx >> 11];   // 2048 groups of 8 per (n,c)
    float4 r0, r1;
    r0.x = gt * a0.x + xv0.x;
    r0.y = gt * a0.y + xv0.y;
    r0.z = gt * a1.x + xv0.z;
    r0.w = gt * a1.y + xv0.w;
    r1.x = gt * a2.x + xv1.x;
    r1.y = gt * a2.y + xv1.y;
    r1.z = gt * a3.x + xv1.z;
    r1.w = gt * a3.y + xv1.w;
    ((float4*)o)[2 * idx]     = r0;
    ((float4*)o)[2 * idx + 1] = r1;
}

// ---------------------------------------------------------------------------
extern "C" void kernel_launch(void* const* d_in, const int* in_sizes, int n_in,
                              void* d_out, int out_size)
{
    const float* x    = (const float*)d_in[0];
    const float* Wq   = (const float*)d_in[1];
    const float* Wk   = (const float*)d_in[2];
    const float* Wv   = (const float*)d_in[3];
    const float* W1   = (const float*)d_in[4];
    const float* W2   = (const float*)d_in[5];
    const float* gama = (const float*)d_in[6];
    float* out = (float*)d_out;

    cudaFuncSetAttribute(fused_attn, cudaFuncAttributeMaxDynamicSharedMemorySize, SMEM_TOTAL);

    convert_w<<<48, 256>>>(Wq, Wk, Wv);
    fused_attn<<<NB * HH, 256, SMEM_TOTAL>>>(x);
    gate2<<<NB, 256>>>(W1, W2);
    final_k<<<(NB * CCH * HWSZ) / (8 * 256), 256>>>(x, gama, out);
}

// round 16
// speedup vs baseline: 1.1836x; 1.0158x over previous
#include <cuda_runtime.h>
#include <cuda_bf16.h>
#include <math.h>

#define NB   8
#define CCH  256
#define HH   128
#define WW   128
#define HWSZ 16384
#define QKD  64

typedef unsigned int u32;
typedef __nv_bfloat16 bf16;

// ---------------- scratch ----------------
__device__ uint4 g_Wf[24 * 16 * 32];                    // W mma-fragment layout
__device__ __align__(16) bf16 g_attn[(size_t)NB * CCH * HWSZ];  // pre-gate out, bf16
__device__ float g_psum[(size_t)NB * CCH * HH];
__device__ float g_pmax[(size_t)NB * CCH * HH];
__device__ float g_gate[NB * CCH];

// ---------------- helpers ----------------
__device__ __forceinline__ u32 smem_u32(const void* p) {
    u32 a;
    asm("{.reg .u64 t; cvta.to.shared.u64 t, %1; cvt.u32.u64 %0, t;}"
        : "=r"(a) : "l"(p));
    return a;
}
__device__ __forceinline__ void ldsm4(u32* r, u32 a) {
    asm volatile("ldmatrix.sync.aligned.m8n8.x4.shared.b16 {%0,%1,%2,%3},[%4];"
        : "=r"(r[0]), "=r"(r[1]), "=r"(r[2]), "=r"(r[3]) : "r"(a));
}
__device__ __forceinline__ void ldsm4t(u32* r, u32 a) {
    asm volatile("ldmatrix.sync.aligned.m8n8.x4.trans.shared.b16 {%0,%1,%2,%3},[%4];"
        : "=r"(r[0]), "=r"(r[1]), "=r"(r[2]), "=r"(r[3]) : "r"(a));
}
__device__ __forceinline__ void mma_bf(float* d, const u32* a, const u32* b) {
    asm volatile(
        "mma.sync.aligned.m16n8k16.row.col.f32.bf16.bf16.f32 "
        "{%0,%1,%2,%3},{%4,%5,%6,%7},{%8,%9},{%0,%1,%2,%3};"
        : "+f"(d[0]), "+f"(d[1]), "+f"(d[2]), "+f"(d[3])
        : "r"(a[0]), "r"(a[1]), "r"(a[2]), "r"(a[3]), "r"(b[0]), "r"(b[1]));
}
__device__ __forceinline__ u32 packbf(float lo, float hi) {
    u32 r; asm("cvt.rn.bf16x2.f32 %0,%1,%2;" : "=r"(r) : "f"(hi), "f"(lo));
    return r;
}
__device__ __forceinline__ void cp16(u32 dst, const void* src) {
    asm volatile("cp.async.cg.shared.global [%0], [%1], 16;" :: "r"(dst), "l"(src));
}
#define CP_COMMIT() asm volatile("cp.async.commit_group;" ::: "memory")
#define CP_WAIT1()  asm volatile("cp.async.wait_group 1;" ::: "memory")

// ---------------------------------------------------------------------------
__global__ void convert_w(const float* __restrict__ Wq,
                          const float* __restrict__ Wk,
                          const float* __restrict__ Wv)
{
    int tid = blockIdx.x * 256 + threadIdx.x;   // 0..12287
    int mt  = tid >> 9;
    int rem = tid & 511;
    int kt  = rem >> 5;
    int l   = rem & 31;
    int g2 = l >> 2, tq2 = l & 3;
    int r0 = mt * 16 + g2;
    int c0 = kt * 16 + tq2 * 2;

    const float* S; int roff;
    if (r0 < 64)       { S = Wq; roff = r0; }
    else if (r0 < 128) { S = Wk; roff = r0 - 64; }
    else               { S = Wv; roff = r0 - 128; }
    const float* p0 = S + (size_t)roff * CCH;
    const float* p8 = p0 + 8 * CCH;

    uint4 o;
    o.x = packbf(p0[c0],     p0[c0 + 1]);
    o.y = packbf(p8[c0],     p8[c0 + 1]);
    o.z = packbf(p0[c0 + 8], p0[c0 + 9]);
    o.w = packbf(p8[c0 + 8], p8[c0 + 9]);
    g_Wf[tid] = o;
}

// ---------------------------------------------------------------------------
#define XT_PITCH 136
#define QP       136
#define SMEM_TOTAL 211456

// dst[128][QP] = W-block(wt0) @ xt; 8 warps: m0=(w&3)*32 (mf 0..1), n0=(w>>2)*64 (nf 0..7)
__device__ __forceinline__ void gemm_wx(int wt0, const bf16* xt, bf16* dst,
                                        int l, int m0, int n0)
{
    float acc[2][8][4];
#pragma unroll
    for (int a = 0; a < 2; a++)
#pragma unroll
        for (int b = 0; b < 8; b++)
#pragma unroll
            for (int c = 0; c < 4; c++) acc[a][b][c] = 0.f;

    int mt0 = wt0 + (m0 >> 4);
#pragma unroll
    for (int kt = 0; kt < 16; kt++) {
        u32 a[2][4], b[8][2];
#pragma unroll
        for (int mf = 0; mf < 2; mf++) {
            uint4 av = g_Wf[(size_t)((mt0 + mf) * 16 + kt) * 32 + l];
            a[mf][0] = av.x; a[mf][1] = av.y; a[mf][2] = av.z; a[mf][3] = av.w;
        }
        int kk = kt * 16;
        int br  = kk + ((l >> 3) & 1) * 8 + (l & 7);
        int bcl = (l >> 4) * 8;
#pragma unroll
        for (int bi = 0; bi < 4; bi++) {
            u32 r4[4];
            ldsm4t(r4, smem_u32(xt + br * XT_PITCH + n0 + bi * 16 + bcl));
            b[bi * 2][0] = r4[0]; b[bi * 2][1] = r4[1];
            b[bi * 2 + 1][0] = r4[2]; b[bi * 2 + 1][1] = r4[3];
        }
#pragma unroll
        for (int mf = 0; mf < 2; mf++)
#pragma unroll
            for (int nf = 0; nf < 8; nf++)
                mma_bf(acc[mf][nf], a[mf], b[nf]);
    }

    int g = l >> 2, tq = l & 3;
#pragma unroll
    for (int mf = 0; mf < 2; mf++)
#pragma unroll
        for (int nf = 0; nf < 8; nf++) {
            int col = n0 + nf * 8 + tq * 2;
            *(u32*)(dst + (m0 + mf * 16 + g) * QP + col)     = packbf(acc[mf][nf][0], acc[mf][nf][1]);
            *(u32*)(dst + (m0 + mf * 16 + g + 8) * QP + col) = packbf(acc[mf][nf][2], acc[mf][nf][3]);
        }
}

__global__ __launch_bounds__(256, 1) void fused_attn(const float* __restrict__ x)
{
    extern __shared__ char smc[];
    bf16*  xt    = (bf16*)smc;                  // [256][136] bf16
    bf16*  stage = (bf16*)smc;                  // att.V output stage (overlays dead xt)
    bf16*  qk_s  = (bf16*)(smc + 69632);        // [128][136] bf16
    bf16*  att_s = qk_s;                        // overlay after logits
    bf16*  v_s   = (bf16*)(smc + 104448);       // [256][136] bf16
    float* psum  = (float*)(smc + 174080);      // [128][2]
    float* pmax  = psum + 256;                  // [128][2]
    float* inv_s = (float*)(smc + 178176);      // [128]
    float* xf32  = (float*)(smc + 178688);      // 2 x [32][128] fp32 staging

    bf16* outb = g_attn;

    int nh = blockIdx.x, n = nh >> 7, h = nh & 127;
    int t = threadIdx.x, l = t & 31, w = t >> 5;
    int m0 = (w & 3) * 32, n0 = (w >> 2) * 64;

    const float* xg = x + ((size_t)n * CCH * HH + h) * WW;
    u32 xf_base = smem_u32(xf32);

    // ---- prologue: issue chunks 0,1 ----
#pragma unroll
    for (int ch = 0; ch < 2; ch++) {
#pragma unroll
        for (int q = 0; q < 4; q++) {
            int e = t + q * 256;
            int c = e >> 5, i4 = (e & 31) << 2;
            cp16(xf_base + (ch & 1) * 16384 + (c * 128 + i4) * 4,
                 xg + ((size_t)(ch * 32 + c) * HWSZ) + i4);
        }
        CP_COMMIT();
    }

    // ---- pipelined x-convert + qk GEMM ----
    float accq[2][8][4];
#pragma unroll
    for (int a = 0; a < 2; a++)
#pragma unroll
        for (int b = 0; b < 8; b++)
#pragma unroll
            for (int c = 0; c < 4; c++) accq[a][b][c] = 0.f;

    int mt0q = (m0 >> 4);

#pragma unroll 1
    for (int ch = 0; ch < 8; ch++) {
        CP_WAIT1();
        __syncthreads();                         // chunk ch visible to all

        const float* src = xf32 + (ch & 1) * 4096;
#pragma unroll
        for (int q = 0; q < 4; q++) {
            int e = t + q * 256;
            int c = e >> 5, i4 = (e & 31) << 2;
            float4 v4 = *(const float4*)(src + c * 128 + i4);
            uint2 o;
            o.x = packbf(v4.x, v4.y);
            o.y = packbf(v4.z, v4.w);
            *(uint2*)(xt + (ch * 32 + c) * XT_PITCH + i4) = o;
        }
        __syncthreads();                         // buffer free + xt chunk ready

        if (ch < 6) {
#pragma unroll
            for (int q = 0; q < 4; q++) {
                int e = t + q * 256;
                int c = e >> 5, i4 = (e & 31) << 2;
                cp16(xf_base + (ch & 1) * 16384 + (c * 128 + i4) * 4,
                     xg + ((size_t)((ch + 2) * 32 + c) * HWSZ) + i4);
            }
            CP_COMMIT();
        }

        // qk GEMM: 2 kt steps on this chunk
#pragma unroll
        for (int kt2 = 0; kt2 < 2; kt2++) {
            int kt = ch * 2 + kt2;
            u32 a[2][4], b[8][2];
#pragma unroll
            for (int mf = 0; mf < 2; mf++) {
                uint4 av = g_Wf[(size_t)((mt0q + mf) * 16 + kt) * 32 + l];
                a[mf][0] = av.x; a[mf][1] = av.y; a[mf][2] = av.z; a[mf][3] = av.w;
            }
            int kk = kt * 16;
            int br  = kk + ((l >> 3) & 1) * 8 + (l & 7);
            int bcl = (l >> 4) * 8;
#pragma unroll
            for (int bi = 0; bi < 4; bi++) {
                u32 r4[4];
                ldsm4t(r4, smem_u32(xt + br * XT_PITCH + n0 + bi * 16 + bcl));
                b[bi * 2][0] = r4[0]; b[bi * 2][1] = r4[1];
                b[bi * 2 + 1][0] = r4[2]; b[bi * 2 + 1][1] = r4[3];
            }
#pragma unroll
            for (int mf = 0; mf < 2; mf++)
#pragma unroll
                for (int nf = 0; nf < 8; nf++)
                    mma_bf(accq[mf][nf], a[mf], b[nf]);
        }
    }

    // qk epilogue -> qk_s
    {
        int g = l >> 2, tq = l & 3;
#pragma unroll
        for (int mf = 0; mf < 2; mf++)
#pragma unroll
            for (int nf = 0; nf < 8; nf++) {
                int col = n0 + nf * 8 + tq * 2;
                *(u32*)(qk_s + (m0 + mf * 16 + g) * QP + col)     = packbf(accq[mf][nf][0], accq[mf][nf][1]);
                *(u32*)(qk_s + (m0 + mf * 16 + g + 8) * QP + col) = packbf(accq[mf][nf][2], accq[mf][nf][3]);
            }
    }

    // ---- v projections (xt fully resident) ----
    gemm_wx(8,  xt, v_s,            l, m0, n0);
    gemm_wx(16, xt, v_s + 128 * QP, l, m0, n0);
    __syncthreads();

    // ---- logits in registers + register softmax ----
    {
        float acc[2][8][4];
#pragma unroll
        for (int a = 0; a < 2; a++)
#pragma unroll
            for (int b = 0; b < 8; b++)
#pragma unroll
                for (int c = 0; c < 4; c++) acc[a][b][c] = 0.f;

        const bf16* k_s = qk_s + 64 * QP;
#pragma unroll
        for (int ks = 0; ks < 4; ks++) {
            int k0 = ks * 16;
            u32 a[2][4], b[8][2];
            int ar  = k0 + ((l >> 4) << 3) + (l & 7);
            int acl = ((l >> 3) & 1) * 8;
#pragma unroll
            for (int mf = 0; mf < 2; mf++)
                ldsm4t(a[mf], smem_u32(qk_s + ar * QP + m0 + mf * 16 + acl));
            int br  = k0 + ((l >> 3) & 1) * 8 + (l & 7);
            int bcl = (l >> 4) * 8;
#pragma unroll
            for (int bi = 0; bi < 4; bi++) {
                u32 r4[4];
                ldsm4t(r4, smem_u32(k_s + br * QP + n0 + bi * 16 + bcl));
                b[bi * 2][0] = r4[0]; b[bi * 2][1] = r4[1];
                b[bi * 2 + 1][0] = r4[2]; b[bi * 2 + 1][1] = r4[3];
            }
#pragma unroll
            for (int mf = 0; mf < 2; mf++)
#pragma unroll
                for (int nf = 0; nf < 8; nf++)
                    mma_bf(acc[mf][nf], a[mf], b[nf]);
        }

        int g = l >> 2, tq = l & 3, wj = w >> 2;

#pragma unroll
        for (int mf = 0; mf < 2; mf++) {
            float rl = -1e30f, rh = -1e30f;
#pragma unroll
            for (int nf = 0; nf < 8; nf++) {
                rl = fmaxf(rl, fmaxf(acc[mf][nf][0], acc[mf][nf][1]));
                rh = fmaxf(rh, fmaxf(acc[mf][nf][2], acc[mf][nf][3]));
            }
            rl = fmaxf(rl, __shfl_xor_sync(0xffffffffu, rl, 1));
            rl = fmaxf(rl, __shfl_xor_sync(0xffffffffu, rl, 2));
            rh = fmaxf(rh, __shfl_xor_sync(0xffffffffu, rh, 1));
            rh = fmaxf(rh, __shfl_xor_sync(0xffffffffu, rh, 2));
            if (tq == 0) {
                pmax[(m0 + mf * 16 + g) * 2 + wj]     = rl;
                pmax[(m0 + mf * 16 + g + 8) * 2 + wj] = rh;
            }
        }
        __syncthreads();   // max partials visible; ALL qk ldsm reads complete

#pragma unroll
        for (int mf = 0; mf < 2; mf++) {
            int il = m0 + mf * 16 + g, ih = il + 8;
            float Ml = fmaxf(pmax[il * 2], pmax[il * 2 + 1]);
            float Mh = fmaxf(pmax[ih * 2], pmax[ih * 2 + 1]);
            float sl = 0.f, sh = 0.f;
#pragma unroll
            for (int nf = 0; nf < 8; nf++) {
                float e0 = __expf(acc[mf][nf][0] - Ml);
                float e1 = __expf(acc[mf][nf][1] - Ml);
                float e2 = __expf(acc[mf][nf][2] - Mh);
                float e3 = __expf(acc[mf][nf][3] - Mh);
                sl += e0 + e1; sh += e2 + e3;
                int j = n0 + nf * 8 + tq * 2;
                *(u32*)(att_s + il * QP + j) = packbf(e0, e1);
                *(u32*)(att_s + ih * QP + j) = packbf(e2, e3);
            }
            sl += __shfl_xor_sync(0xffffffffu, sl, 1);
            sl += __shfl_xor_sync(0xffffffffu, sl, 2);
            sh += __shfl_xor_sync(0xffffffffu, sh, 1);
            sh += __shfl_xor_sync(0xffffffffu, sh, 2);
            if (tq == 0) {
                psum[il * 2 + wj] = sl;
                psum[ih * 2 + wj] = sh;
            }
        }
        __syncthreads();

        if (t < 128)
            inv_s[t] = 1.f / (psum[t * 2] + psum[t * 2 + 1]);
        __syncthreads();
    }

    // ---- att . V : out[c][i], 2 chunks of 128 channels ----
    int wg = w >> 2;
    for (int cc = 0; cc < 2; cc++) {
        const bf16* vc = v_s + (size_t)cc * 128 * QP;

        float acc[2][8][4];
#pragma unroll
        for (int a = 0; a < 2; a++)
#pragma unroll
            for (int b = 0; b < 8; b++)
#pragma unroll
                for (int c = 0; c < 4; c++) acc[a][b][c] = 0.f;

#pragma unroll
        for (int ks = 0; ks < 8; ks++) {
            int k0 = ks * 16;
            u32 a[2][4], b[8][2];
            int ar  = ((l >> 3) & 1) * 8 + (l & 7);
            int acl = k0 + (l >> 4) * 8;
#pragma unroll
            for (int mf = 0; mf < 2; mf++)
                ldsm4(a[mf], smem_u32(vc + (m0 + mf * 16 + ar) * QP + acl));
            int brr = (l >> 4) * 8 + (l & 7);
            int bcl = k0 + ((l >> 3) & 1) * 8;
#pragma unroll
            for (int bi = 0; bi < 4; bi++) {
                u32 r4[4];
                ldsm4(r4, smem_u32(att_s + (n0 + bi * 16 + brr) * QP + bcl));
                b[bi * 2][0] = r4[0]; b[bi * 2][1] = r4[1];
                b[bi * 2 + 1][0] = r4[2]; b[bi * 2 + 1][1] = r4[3];
            }
#pragma unroll
            for (int mf = 0; mf < 2; mf++)
#pragma unroll
                for (int nf = 0; nf < 8; nf++)
                    mma_bf(acc[mf][nf], a[mf], b[nf]);
        }

        // epilogue: scale, stage to smem (dead xt region), reduce partials
        int g = l >> 2, tq = l & 3;
#pragma unroll
        for (int mf = 0; mf < 2; mf++) {
            float rs0 = 0.f, rs1 = 0.f, rm0 = -1e30f, rm1 = -1e30f;
#pragma unroll
            for (int nf = 0; nf < 8; nf++) {
                int i = n0 + nf * 8 + tq * 2;
                float2 iv = *(float2*)(inv_s + i);
                int c = m0 + mf * 16 + g;
                float o0 = acc[mf][nf][0] * iv.x;
                float o1 = acc[mf][nf][1] * iv.y;
                float o2 = acc[mf][nf][2] * iv.x;
                float o3 = acc[mf][nf][3] * iv.y;
                *(u32*)(stage + c * QP + i)       = packbf(o0, o1);
                *(u32*)(stage + (c + 8) * QP + i) = packbf(o2, o3);
                rs0 += o0 + o1; rm0 = fmaxf(rm0, fmaxf(o0, o1));
                rs1 += o2 + o3; rm1 = fmaxf(rm1, fmaxf(o2, o3));
            }
#pragma unroll
            for (int off = 1; off < 4; off <<= 1) {
                rs0 += __shfl_xor_sync(0xffffffffu, rs0, off);
                rs1 += __shfl_xor_sync(0xffffffffu, rs1, off);
                rm0 = fmaxf(rm0, __shfl_xor_sync(0xffffffffu, rm0, off));
                rm1 = fmaxf(rm1, __shfl_xor_sync(0xffffffffu, rm1, off));
            }
            if (tq == 0) {
                int c128 = m0 + mf * 16 + g;
                psum[c128 * 2 + wg]       = rs0;
                psum[(c128 + 8) * 2 + wg] = rs1;
                pmax[c128 * 2 + wg]       = rm0;
                pmax[(c128 + 8) * 2 + wg] = rm1;
            }
        }
        __syncthreads();   // stage + partials visible

        // coalesced gmem write: 128 rows x 128 i bf16, 16B per thread-slot
#pragma unroll
        for (int q = 0; q < 8; q++) {
            int e = t + q * 256;                // 0..2047
            int row = e >> 4, c8 = (e & 15) * 8;
            uint4 vv = *(const uint4*)(stage + row * QP + c8);
            size_t dst = (((size_t)n * CCH + cc * 128 + row) * HH + h) * (size_t)WW + c8;
            *(uint4*)(outb + dst) = vv;
        }
        if (t < 128) {
            float s = psum[t * 2] + psum[t * 2 + 1];
            float m = fmaxf(pmax[t * 2], pmax[t * 2 + 1]);
            size_t nc = (size_t)n * CCH + cc * 128 + t;
            g_psum[nc * HH + h] = s;
            g_pmax[nc * HH + h] = m;
        }
        __syncthreads();   // stage reusable for next cc
    }
}

// ---------------------------------------------------------------------------
__global__ void gate2(const float* __restrict__ W1, const float* __restrict__ W2)
{
    __shared__ float avg[CCH], mx[CCH], h1[2][16];
    int n = blockIdx.x, t = threadIdx.x;

    {
        const float4* ps = (const float4*)(g_psum + ((size_t)n * CCH + t) * HH);
        const float4* pm = (const float4*)(g_pmax + ((size_t)n * CCH + t) * HH);
        float s = 0.f, m = -1e30f;
#pragma unroll 8
        for (int q = 0; q < 32; q++) {
            float4 a = ps[q];
            s += a.x + a.y + a.z + a.w;
            float4 b = pm[q];
            m = fmaxf(m, fmaxf(fmaxf(b.x, b.y), fmaxf(b.z, b.w)));
        }
        avg[t] = s * (1.f / HWSZ);
        mx[t]  = m;
    }
    __syncthreads();

    {
        int dot = t >> 3, part = t & 7;
        int path = dot >> 4, r = dot & 15;
        const float* z  = path ? mx : avg;
        const float* wr = W1 + r * CCH + part * 32;
        float acc = 0.f;
#pragma unroll 8
        for (int c = 0; c < 32; c++) acc += wr[c] * z[part * 32 + c];
        acc += __shfl_xor_sync(0xffffffffu, acc, 1);
        acc += __shfl_xor_sync(0xffffffffu, acc, 2);
        acc += __shfl_xor_sync(0xffffffffu, acc, 4);
        if (part == 0) h1[path][r] = fmaxf(acc, 0.f);
    }
    __syncthreads();

    {
        float g = 0.f;
#pragma unroll
        for (int r = 0; r < 16; r++)
            g += W2[t * 16 + r] * (h1[0][r] + h1[1][r]);
        g_gate[n * CCH + t] = 1.f / (1.f + __expf(-g));
    }
}

__global__ void final_k(const float* __restrict__ x,
                        const float* __restrict__ gama,
                        float* __restrict__ o)
{
    size_t idx = (size_t)blockIdx.x * blockDim.x + threadIdx.x;   // per 8 elements
    float g = gama[0];
    uint4 av = ((const uint4*)g_attn)[idx];
    float4 xv0 = ((const float4*)x)[2 * idx];
    float4 xv1 = ((const float4*)x)[2 * idx + 1];
    float2 a0 = __bfloat1622float2(*(const __nv_bfloat162*)&av.x);
    float2 a1 = __bfloat1622float2(*(const __nv_bfloat162*)&av.y);
    float2 a2 = __bfloat1622float2(*(const __nv_bfloat162*)&av.z);
    float2 a3 = __bfloat1622float2(*(const __nv_bfloat162*)&av.w);
    float gt = g * g_gate[idx >> 11];
    float4 r0, r1;
    r0.x = gt * a0.x + xv0.x;
    r0.y = gt * a0.y + xv0.y;
    r0.z = gt * a1.x + xv0.z;
    r0.w = gt * a1.y + xv0.w;
    r1.x = gt * a2.x + xv1.x;
    r1.y = gt * a2.y + xv1.y;
    r1.z = gt * a3.x + xv1.z;
    r1.w = gt * a3.y + xv1.w;
    ((float4*)o)[2 * idx]     = r0;
    ((float4*)o)[2 * idx + 1] = r1;
}

// ---------------------------------------------------------------------------
extern "C" void kernel_launch(void* const* d_in, const int* in_sizes, int n_in,
                              void* d_out, int out_size)
{
    const float* x    = (const float*)d_in[0];
    const float* Wq   = (const float*)d_in[1];
    const float* Wk   = (const float*)d_in[2];
    const float* Wv   = (const float*)d_in[3];
    const float* W1   = (const float*)d_in[4];
    const float* W2   = (const float*)d_in[5];
    const float* gama = (const float*)d_in[6];
    float* out = (float*)d_out;

    cudaFuncSetAttribute(fused_attn, cudaFuncAttributeMaxDynamicSharedMemorySize, SMEM_TOTAL);

    convert_w<<<48, 256>>>(Wq, Wk, Wv);
    fused_attn<<<NB * HH, 256, SMEM_TOTAL>>>(x);
    gate2<<<NB, 256>>>(W1, W2);
    final_k<<<(NB * CCH * HWSZ) / (8 * 256), 256>>>(x, gama, out);
}

// round 17
// speedup vs baseline: 1.1853x; 1.0014x over previous
#include <cuda_runtime.h>
#include <cuda_bf16.h>
#include <math.h>

#define NB   8
#define CCH  256
#define HH   128
#define WW   128
#define HWSZ 16384
#define QKD  64

typedef unsigned int u32;
typedef __nv_bfloat16 bf16;

// ---------------- scratch ----------------
__device__ uint4 g_Wf[24 * 16 * 32];                    // W mma-fragment layout
__device__ __align__(16) bf16 g_attn[(size_t)NB * CCH * HWSZ];  // pre-gate out, bf16
__device__ float g_psum[(size_t)NB * CCH * HH];
__device__ float g_pmax[(size_t)NB * CCH * HH];
__device__ float g_gate[NB * CCH];

// ---------------- helpers ----------------
__device__ __forceinline__ u32 smem_u32(const void* p) {
    u32 a;
    asm("{.reg .u64 t; cvta.to.shared.u64 t, %1; cvt.u32.u64 %0, t;}"
        : "=r"(a) : "l"(p));
    return a;
}
__device__ __forceinline__ void ldsm4(u32* r, u32 a) {
    asm volatile("ldmatrix.sync.aligned.m8n8.x4.shared.b16 {%0,%1,%2,%3},[%4];"
        : "=r"(r[0]), "=r"(r[1]), "=r"(r[2]), "=r"(r[3]) : "r"(a));
}
__device__ __forceinline__ void ldsm4t(u32* r, u32 a) {
    asm volatile("ldmatrix.sync.aligned.m8n8.x4.trans.shared.b16 {%0,%1,%2,%3},[%4];"
        : "=r"(r[0]), "=r"(r[1]), "=r"(r[2]), "=r"(r[3]) : "r"(a));
}
__device__ __forceinline__ void mma_bf(float* d, const u32* a, const u32* b) {
    asm volatile(
        "mma.sync.aligned.m16n8k16.row.col.f32.bf16.bf16.f32 "
        "{%0,%1,%2,%3},{%4,%5,%6,%7},{%8,%9},{%0,%1,%2,%3};"
        : "+f"(d[0]), "+f"(d[1]), "+f"(d[2]), "+f"(d[3])
        : "r"(a[0]), "r"(a[1]), "r"(a[2]), "r"(a[3]), "r"(b[0]), "r"(b[1]));
}
__device__ __forceinline__ u32 packbf(float lo, float hi) {
    u32 r; asm("cvt.rn.bf16x2.f32 %0,%1,%2;" : "=r"(r) : "f"(hi), "f"(lo));
    return r;
}
__device__ __forceinline__ void cp16(u32 dst, const void* src) {
    asm volatile("cp.async.cg.shared.global [%0], [%1], 16;" :: "r"(dst), "l"(src));
}
#define CP_COMMIT() asm volatile("cp.async.commit_group;" ::: "memory")
#define CP_WAIT1()  asm volatile("cp.async.wait_group 1;" ::: "memory")

// ---------------------------------------------------------------------------
__global__ void convert_w(const float* __restrict__ Wq,
                          const float* __restrict__ Wk,
                          const float* __restrict__ Wv)
{
    int tid = blockIdx.x * 256 + threadIdx.x;   // 0..12287
    int mt  = tid >> 9;
    int rem = tid & 511;
    int kt  = rem >> 5;
    int l   = rem & 31;
    int g2 = l >> 2, tq2 = l & 3;
    int r0 = mt * 16 + g2;
    int c0 = kt * 16 + tq2 * 2;

    const float* S; int roff;
    if (r0 < 64)       { S = Wq; roff = r0; }
    else if (r0 < 128) { S = Wk; roff = r0 - 64; }
    else               { S = Wv; roff = r0 - 128; }
    const float* p0 = S + (size_t)roff * CCH;
    const float* p8 = p0 + 8 * CCH;

    uint4 o;
    o.x = packbf(p0[c0],     p0[c0 + 1]);
    o.y = packbf(p8[c0],     p8[c0 + 1]);
    o.z = packbf(p0[c0 + 8], p0[c0 + 9]);
    o.w = packbf(p8[c0 + 8], p8[c0 + 9]);
    g_Wf[tid] = o;
}

// ---------------------------------------------------------------------------
#define XT_PITCH 136
#define QP       136
#define SMEM_TOTAL 211456

__global__ __launch_bounds__(256, 1) void fused_attn(const float* __restrict__ x)
{
    extern __shared__ char smc[];
    bf16*  xt    = (bf16*)smc;                  // [256][136] bf16
    bf16*  stage = (bf16*)smc;                  // att.V output stage (overlays dead xt)
    bf16*  qk_s  = (bf16*)(smc + 69632);        // [128][136] bf16
    bf16*  att_s = qk_s;                        // overlay after logits
    bf16*  v_s   = (bf16*)(smc + 104448);       // [256][136] bf16
    float* psum  = (float*)(smc + 174080);      // [128][2]
    float* pmax  = psum + 256;                  // [128][2]
    float* inv_s = (float*)(smc + 178176);      // [128]
    float* xf32  = (float*)(smc + 178688);      // 2 x [32][128] fp32 staging

    bf16* outb = g_attn;

    int nh = blockIdx.x, n = nh >> 7, h = nh & 127;
    int t = threadIdx.x, l = t & 31, w = t >> 5;
    int m0 = (w & 3) * 32, n0 = (w >> 2) * 64;

    const float* xg = x + ((size_t)n * CCH * HH + h) * WW;
    u32 xf_base = smem_u32(xf32);

    // ---- prologue: issue chunks 0,1 ----
#pragma unroll
    for (int ch = 0; ch < 2; ch++) {
#pragma unroll
        for (int q = 0; q < 4; q++) {
            int e = t + q * 256;
            int c = e >> 5, i4 = (e & 31) << 2;
            cp16(xf_base + (ch & 1) * 16384 + (c * 128 + i4) * 4,
                 xg + ((size_t)(ch * 32 + c) * HWSZ) + i4);
        }
        CP_COMMIT();
    }

    // ---- pipelined x-convert + qk GEMM ----
    float accq[2][8][4];
#pragma unroll
    for (int a = 0; a < 2; a++)
#pragma unroll
        for (int b = 0; b < 8; b++)
#pragma unroll
            for (int c = 0; c < 4; c++) accq[a][b][c] = 0.f;

    int mt0q = (m0 >> 4);

#pragma unroll 1
    for (int ch = 0; ch < 8; ch++) {
        CP_WAIT1();
        __syncthreads();                         // chunk ch visible to all

        const float* src = xf32 + (ch & 1) * 4096;
#pragma unroll
        for (int q = 0; q < 4; q++) {
            int e = t + q * 256;
            int c = e >> 5, i4 = (e & 31) << 2;
            float4 v4 = *(const float4*)(src + c * 128 + i4);
            uint2 o;
            o.x = packbf(v4.x, v4.y);
            o.y = packbf(v4.z, v4.w);
            *(uint2*)(xt + (ch * 32 + c) * XT_PITCH + i4) = o;
        }
        __syncthreads();                         // buffer free + xt chunk ready

        if (ch < 6) {
#pragma unroll
            for (int q = 0; q < 4; q++) {
                int e = t + q * 256;
                int c = e >> 5, i4 = (e & 31) << 2;
                cp16(xf_base + (ch & 1) * 16384 + (c * 128 + i4) * 4,
                     xg + ((size_t)((ch + 2) * 32 + c) * HWSZ) + i4);
            }
            CP_COMMIT();
        }

        // qk GEMM: 2 kt steps on this chunk
#pragma unroll
        for (int kt2 = 0; kt2 < 2; kt2++) {
            int kt = ch * 2 + kt2;
            u32 a[2][4], b[8][2];
#pragma unroll
            for (int mf = 0; mf < 2; mf++) {
                uint4 av = g_Wf[(size_t)((mt0q + mf) * 16 + kt) * 32 + l];
                a[mf][0] = av.x; a[mf][1] = av.y; a[mf][2] = av.z; a[mf][3] = av.w;
            }
            int kk = kt * 16;
            int br  = kk + ((l >> 3) & 1) * 8 + (l & 7);
            int bcl = (l >> 4) * 8;
#pragma unroll
            for (int bi = 0; bi < 4; bi++) {
                u32 r4[4];
                ldsm4t(r4, smem_u32(xt + br * XT_PITCH + n0 + bi * 16 + bcl));
                b[bi * 2][0] = r4[0]; b[bi * 2][1] = r4[1];
                b[bi * 2 + 1][0] = r4[2]; b[bi * 2 + 1][1] = r4[3];
            }
#pragma unroll
            for (int mf = 0; mf < 2; mf++)
#pragma unroll
                for (int nf = 0; nf < 8; nf++)
                    mma_bf(accq[mf][nf], a[mf], b[nf]);
        }
    }

    // qk epilogue -> qk_s
    {
        int g = l >> 2, tq = l & 3;
#pragma unroll
        for (int mf = 0; mf < 2; mf++)
#pragma unroll
            for (int nf = 0; nf < 8; nf++) {
                int col = n0 + nf * 8 + tq * 2;
                *(u32*)(qk_s + (m0 + mf * 16 + g) * QP + col)     = packbf(accq[mf][nf][0], accq[mf][nf][1]);
                *(u32*)(qk_s + (m0 + mf * 16 + g + 8) * QP + col) = packbf(accq[mf][nf][2], accq[mf][nf][3]);
            }
    }

    // ---- fused v1+v2 projections: shared B fragments per kt ----
    {
        float accv[2][2][8][4];
#pragma unroll
        for (int bk = 0; bk < 2; bk++)
#pragma unroll
            for (int a = 0; a < 2; a++)
#pragma unroll
                for (int b = 0; b < 8; b++)
#pragma unroll
                    for (int c = 0; c < 4; c++) accv[bk][a][b][c] = 0.f;

        int mt0v = 8 + (m0 >> 4);   // v1 tiles start at 8, v2 at 16
#pragma unroll
        for (int kt = 0; kt < 16; kt++) {
            u32 a[2][2][4], b[8][2];
#pragma unroll
            for (int bk = 0; bk < 2; bk++)
#pragma unroll
                for (int mf = 0; mf < 2; mf++) {
                    uint4 av = g_Wf[(size_t)((mt0v + bk * 8 + mf) * 16 + kt) * 32 + l];
                    a[bk][mf][0] = av.x; a[bk][mf][1] = av.y;
                    a[bk][mf][2] = av.z; a[bk][mf][3] = av.w;
                }
            int kk = kt * 16;
            int br  = kk + ((l >> 3) & 1) * 8 + (l & 7);
            int bcl = (l >> 4) * 8;
#pragma unroll
            for (int bi = 0; bi < 4; bi++) {
                u32 r4[4];
                ldsm4t(r4, smem_u32(xt + br * XT_PITCH + n0 + bi * 16 + bcl));
                b[bi * 2][0] = r4[0]; b[bi * 2][1] = r4[1];
                b[bi * 2 + 1][0] = r4[2]; b[bi * 2 + 1][1] = r4[3];
            }
#pragma unroll
            for (int bk = 0; bk < 2; bk++)
#pragma unroll
                for (int mf = 0; mf < 2; mf++)
#pragma unroll
                    for (int nf = 0; nf < 8; nf++)
                        mma_bf(accv[bk][mf][nf], a[bk][mf], b[nf]);
        }

        int g = l >> 2, tq = l & 3;
#pragma unroll
        for (int bk = 0; bk < 2; bk++) {
            bf16* dst = v_s + (size_t)bk * 128 * QP;
#pragma unroll
            for (int mf = 0; mf < 2; mf++)
#pragma unroll
                for (int nf = 0; nf < 8; nf++) {
                    int col = n0 + nf * 8 + tq * 2;
                    *(u32*)(dst + (m0 + mf * 16 + g) * QP + col)     = packbf(accv[bk][mf][nf][0], accv[bk][mf][nf][1]);
                    *(u32*)(dst + (m0 + mf * 16 + g + 8) * QP + col) = packbf(accv[bk][mf][nf][2], accv[bk][mf][nf][3]);
                }
        }
    }
    __syncthreads();

    // ---- logits in registers + register softmax ----
    {
        float acc[2][8][4];
#pragma unroll
        for (int a = 0; a < 2; a++)
#pragma unroll
            for (int b = 0; b < 8; b++)
#pragma unroll
                for (int c = 0; c < 4; c++) acc[a][b][c] = 0.f;

        const bf16* k_s = qk_s + 64 * QP;
#pragma unroll
        for (int ks = 0; ks < 4; ks++) {
            int k0 = ks * 16;
            u32 a[2][4], b[8][2];
            int ar  = k0 + ((l >> 4) << 3) + (l & 7);
            int acl = ((l >> 3) & 1) * 8;
#pragma unroll
            for (int mf = 0; mf < 2; mf++)
                ldsm4t(a[mf], smem_u32(qk_s + ar * QP + m0 + mf * 16 + acl));
            int br  = k0 + ((l >> 3) & 1) * 8 + (l & 7);
            int bcl = (l >> 4) * 8;
#pragma unroll
            for (int bi = 0; bi < 4; bi++) {
                u32 r4[4];
                ldsm4t(r4, smem_u32(k_s + br * QP + n0 + bi * 16 + bcl));
                b[bi * 2][0] = r4[0]; b[bi * 2][1] = r4[1];
                b[bi * 2 + 1][0] = r4[2]; b[bi * 2 + 1][1] = r4[3];
            }
#pragma unroll
            for (int mf = 0; mf < 2; mf++)
#pragma unroll
                for (int nf = 0; nf < 8; nf++)
                    mma_bf(acc[mf][nf], a[mf], b[nf]);
        }

        int g = l >> 2, tq = l & 3, wj = w >> 2;

#pragma unroll
        for (int mf = 0; mf < 2; mf++) {
            float rl = -1e30f, rh = -1e30f;
#pragma unroll
            for (int nf = 0; nf < 8; nf++) {
                rl = fmaxf(rl, fmaxf(acc[mf][nf][0], acc[mf][nf][1]));
                rh = fmaxf(rh, fmaxf(acc[mf][nf][2], acc[mf][nf][3]));
            }
            rl = fmaxf(rl, __shfl_xor_sync(0xffffffffu, rl, 1));
            rl = fmaxf(rl, __shfl_xor_sync(0xffffffffu, rl, 2));
            rh = fmaxf(rh, __shfl_xor_sync(0xffffffffu, rh, 1));
            rh = fmaxf(rh, __shfl_xor_sync(0xffffffffu, rh, 2));
            if (tq == 0) {
                pmax[(m0 + mf * 16 + g) * 2 + wj]     = rl;
                pmax[(m0 + mf * 16 + g + 8) * 2 + wj] = rh;
            }
        }
        __syncthreads();   // max partials visible; ALL qk ldsm reads complete

#pragma unroll
        for (int mf = 0; mf < 2; mf++) {
            int il = m0 + mf * 16 + g, ih = il + 8;
            float Ml = fmaxf(pmax[il * 2], pmax[il * 2 + 1]);
            float Mh = fmaxf(pmax[ih * 2], pmax[ih * 2 + 1]);
            float sl = 0.f, sh = 0.f;
#pragma unroll
            for (int nf = 0; nf < 8; nf++) {
                float e0 = __expf(acc[mf][nf][0] - Ml);
                float e1 = __expf(acc[mf][nf][1] - Ml);
                float e2 = __expf(acc[mf][nf][2] - Mh);
                float e3 = __expf(acc[mf][nf][3] - Mh);
                sl += e0 + e1; sh += e2 + e3;
                int j = n0 + nf * 8 + tq * 2;
                *(u32*)(att_s + il * QP + j) = packbf(e0, e1);
                *(u32*)(att_s + ih * QP + j) = packbf(e2, e3);
            }
            sl += __shfl_xor_sync(0xffffffffu, sl, 1);
            sl += __shfl_xor_sync(0xffffffffu, sl, 2);
            sh += __shfl_xor_sync(0xffffffffu, sh, 1);
            sh += __shfl_xor_sync(0xffffffffu, sh, 2);
            if (tq == 0) {
                psum[il * 2 + wj] = sl;
                psum[ih * 2 + wj] = sh;
            }
        }
        __syncthreads();

        if (t < 128)
            inv_s[t] = 1.f / (psum[t * 2] + psum[t * 2 + 1]);
        __syncthreads();
    }

    // ---- att . V : out[c][i], 2 chunks of 128 channels ----
    int wg = w >> 2;
    for (int cc = 0; cc < 2; cc++) {
        const bf16* vc = v_s + (size_t)cc * 128 * QP;

        float acc[2][8][4];
#pragma unroll
        for (int a = 0; a < 2; a++)
#pragma unroll
            for (int b = 0; b < 8; b++)
#pragma unroll
                for (int c = 0; c < 4; c++) acc[a][b][c] = 0.f;

#pragma unroll
        for (int ks = 0; ks < 8; ks++) {
            int k0 = ks * 16;
            u32 a[2][4], b[8][2];
            int ar  = ((l >> 3) & 1) * 8 + (l & 7);
            int acl = k0 + (l >> 4) * 8;
#pragma unroll
            for (int mf = 0; mf < 2; mf++)
                ldsm4(a[mf], smem_u32(vc + (m0 + mf * 16 + ar) * QP + acl));
            int brr = (l >> 4) * 8 + (l & 7);
            int bcl = k0 + ((l >> 3) & 1) * 8;
#pragma unroll
            for (int bi = 0; bi < 4; bi++) {
                u32 r4[4];
                ldsm4(r4, smem_u32(att_s + (n0 + bi * 16 + brr) * QP + bcl));
                b[bi * 2][0] = r4[0]; b[bi * 2][1] = r4[1];
                b[bi * 2 + 1][0] = r4[2]; b[bi * 2 + 1][1] = r4[3];
            }
#pragma unroll
            for (int mf = 0; mf < 2; mf++)
#pragma unroll
                for (int nf = 0; nf < 8; nf++)
                    mma_bf(acc[mf][nf], a[mf], b[nf]);
        }

        // epilogue: scale, stage to smem (dead xt region), reduce partials
        int g = l >> 2, tq = l & 3;
#pragma unroll
        for (int mf = 0; mf < 2; mf++) {
            float rs0 = 0.f, rs1 = 0.f, rm0 = -1e30f, rm1 = -1e30f;
#pragma unroll
            for (int nf = 0; nf < 8; nf++) {
                int i = n0 + nf * 8 + tq * 2;
                float2 iv = *(float2*)(inv_s + i);
                int c = m0 + mf * 16 + g;
                float o0 = acc[mf][nf][0] * iv.x;
                float o1 = acc[mf][nf][1] * iv.y;
                float o2 = acc[mf][nf][2] * iv.x;
                float o3 = acc[mf][nf][3] * iv.y;
                *(u32*)(stage + c * QP + i)       = packbf(o0, o1);
                *(u32*)(stage + (c + 8) * QP + i) = packbf(o2, o3);
                rs0 += o0 + o1; rm0 = fmaxf(rm0, fmaxf(o0, o1));
                rs1 += o2 + o3; rm1 = fmaxf(rm1, fmaxf(o2, o3));
            }
#pragma unroll
            for (int off = 1; off < 4; off <<= 1) {
                rs0 += __shfl_xor_sync(0xffffffffu, rs0, off);
                rs1 += __shfl_xor_sync(0xffffffffu, rs1, off);
                rm0 = fmaxf(rm0, __shfl_xor_sync(0xffffffffu, rm0, off));
                rm1 = fmaxf(rm1, __shfl_xor_sync(0xffffffffu, rm1, off));
            }
            if (tq == 0) {
                int c128 = m0 + mf * 16 + g;
                psum[c128 * 2 + wg]       = rs0;
                psum[(c128 + 8) * 2 + wg] = rs1;
                pmax[c128 * 2 + wg]       = rm0;
                pmax[(c128 + 8) * 2 + wg] = rm1;
            }
        }
        __syncthreads();   // stage + partials visible

        // coalesced gmem write: 128 rows x 128 i bf16, 16B per thread-slot
#pragma unroll
        for (int q = 0; q < 8; q++) {
            int e = t + q * 256;                // 0..2047
            int row = e >> 4, c8 = (e & 15) * 8;
            uint4 vv = *(const uint4*)(stage + row * QP + c8);
            size_t dst = (((size_t)n * CCH + cc * 128 + row) * HH + h) * (size_t)WW + c8;
            *(uint4*)(outb + dst) = vv;
        }
        if (t < 128) {
            float s = psum[t * 2] + psum[t * 2 + 1];
            float m = fmaxf(pmax[t * 2], pmax[t * 2 + 1]);
            size_t nc = (size_t)n * CCH + cc * 128 + t;
            g_psum[nc * HH + h] = s;
            g_pmax[nc * HH + h] = m;
        }
        __syncthreads();   // stage reusable for next cc
    }
}

// ---------------------------------------------------------------------------
__global__ void gate2(const float* __restrict__ W1, const float* __restrict__ W2)
{
    __shared__ float avg[CCH], mx[CCH], h1[2][16];
    int n = blockIdx.x, t = threadIdx.x;

    {
        const float4* ps = (const float4*)(g_psum + ((size_t)n * CCH + t) * HH);
        const float4* pm = (const float4*)(g_pmax + ((size_t)n * CCH + t) * HH);
        float s = 0.f, m = -1e30f;
#pragma unroll 8
        for (int q = 0; q < 32; q++) {
            float4 a = ps[q];
            s += a.x + a.y + a.z + a.w;
            float4 b = pm[q];
            m = fmaxf(m, fmaxf(fmaxf(b.x, b.y), fmaxf(b.z, b.w)));
        }
        avg[t] = s * (1.f / HWSZ);
        mx[t]  = m;
    }
    __syncthreads();

    {
        int dot = t >> 3, part = t & 7;
        int path = dot >> 4, r = dot & 15;
        const float* z  = path ? mx : avg;
        const float* wr = W1 + r * CCH + part * 32;
        float acc = 0.f;
#pragma unroll 8
        for (int c = 0; c < 32; c++) acc += wr[c] * z[part * 32 + c];
        acc += __shfl_xor_sync(0xffffffffu, acc, 1);
        acc += __shfl_xor_sync(0xffffffffu, acc, 2);
        acc += __shfl_xor_sync(0xffffffffu, acc, 4);
        if (part == 0) h1[path][r] = fmaxf(acc, 0.f);
    }
    __syncthreads();

    {
        float g = 0.f;
#pragma unroll
        for (int r = 0; r < 16; r++)
            g += W2[t * 16 + r] * (h1[0][r] + h1[1][r]);
        g_gate[n * CCH + t] = 1.f / (1.f + __expf(-g));
    }
}

__global__ void final_k(const float* __restrict__ x,
                        const float* __restrict__ gama,
                        float* __restrict__ o)
{
    size_t idx = (size_t)blockIdx.x * blockDim.x + threadIdx.x;   // per 8 elements
    float g = gama[0];
    uint4 av = ((const uint4*)g_attn)[idx];
    float4 xv0 = ((const float4*)x)[2 * idx];
    float4 xv1 = ((const float4*)x)[2 * idx + 1];
    float2 a0 = __bfloat1622float2(*(const __nv_bfloat162*)&av.x);
    float2 a1 = __bfloat1622float2(*(const __nv_bfloat162*)&av.y);
    float2 a2 = __bfloat1622float2(*(const __nv_bfloat162*)&av.z);
    float2 a3 = __bfloat1622float2(*(const __nv_bfloat162*)&av.w);
    float gt = g * g_gate[idx >> 11];
    float4 r0, r1;
    r0.x = gt * a0.x + xv0.x;
    r0.y = gt * a0.y + xv0.y;
    r0.z = gt * a1.x + xv0.z;
    r0.w = gt * a1.y + xv0.w;
    r1.x = gt * a2.x + xv1.x;
    r1.y = gt * a2.y + xv1.y;
    r1.z = gt * a3.x + xv1.z;
    r1.w = gt * a3.y + xv1.w;
    ((float4*)o)[2 * idx]     = r0;
    ((float4*)o)[2 * idx + 1] = r1;
}

// ---------------------------------------------------------------------------
extern "C" void kernel_launch(void* const* d_in, const int* in_sizes, int n_in,
                              void* d_out, int out_size)
{
    const float* x    = (const float*)d_in[0];
    const float* Wq   = (const float*)d_in[1];
    const float* Wk   = (const float*)d_in[2];
    const float* Wv   = (const float*)d_in[3];
    const float* W1   = (const float*)d_in[4];
    const float* W2   = (const float*)d_in[5];
    const float* gama = (const float*)d_in[6];
    float* out = (float*)d_out;

    cudaFuncSetAttribute(fused_attn, cudaFuncAttributeMaxDynamicSharedMemorySize, SMEM_TOTAL);

    convert_w<<<48, 256>>>(Wq, Wk, Wv);
    fused_attn<<<NB * HH, 256, SMEM_TOTAL>>>(x);
    gate2<<<NB, 256>>>(W1, W2);
    final_k<<<(NB * CCH * HWSZ) / (8 * 256), 256>>>(x, gama, out);
}